// round 12
// baseline (speedup 1.0000x reference)
#include <cuda_runtime.h>
#include <cuda_bf16.h>
#include <math.h>
#include <stdint.h>

#define BB 16
#define NN 1024
#define CC 768
#define HH 12
#define DH 64
#define EE 8
#define TT (BB*NN)

// ---------------- scratch (no allocations allowed) ----------------
__device__ float g_h1[(size_t)TT * CC];              // LN1 output (tf32-rounded)
__device__ __nv_bfloat16 g_qb[(size_t)TT * CC];      // Q  [b][h][n][d]  (pre-scaled)
__device__ __nv_bfloat16 g_kb[(size_t)TT * CC];      // K  [b][h][n][d]
__device__ __nv_bfloat16 g_vt[(size_t)TT * CC];      // V  [b][h][d][n]  (transposed)
__device__ float g_o[(size_t)TT * CC];               // attention output (tf32-rounded)
__device__ float g_h2[(size_t)TT * CC];              // LN2 output (full, router)
__device__ float g_h2r[(size_t)TT * CC];             // LN2 output (tf32-rounded, MoE A)
__device__ float g_qkvwr[(size_t)CC * 3 * CC];       // tf32-rounded weights
__device__ float g_projwr[(size_t)CC * CC];
__device__ float g_expwr[(size_t)EE * CC * CC];
__device__ float g_moebuf[2][(size_t)TT * CC];       // MoE slot outputs (weighted)
__device__ int   g_cnt[EE];
__device__ int   g_list[EE * TT];
__device__ float g_wt[EE * TT];
__device__ int   g_slot[EE * TT];

__device__ __forceinline__ unsigned f2tf(float f) {
    unsigned u; asm("cvt.rna.tf32.f32 %0, %1;" : "=r"(u) : "f"(f)); return u;
}
__device__ __forceinline__ float tfround(float f) { return __uint_as_float(f2tf(f)); }
__device__ __forceinline__ unsigned f2bf2(float lo, float hi) {
    __nv_bfloat162 h = __floats2bfloat162_rn(lo, hi);
    return *reinterpret_cast<unsigned*>(&h);
}
__device__ __forceinline__ void mma8(float* c, const unsigned* a, const unsigned* b) {
    asm volatile("mma.sync.aligned.m16n8k8.row.col.f32.tf32.tf32.f32 "
        "{%0,%1,%2,%3}, {%4,%5,%6,%7}, {%8,%9}, {%0,%1,%2,%3};"
        : "+f"(c[0]), "+f"(c[1]), "+f"(c[2]), "+f"(c[3])
        : "r"(a[0]), "r"(a[1]), "r"(a[2]), "r"(a[3]), "r"(b[0]), "r"(b[1]));
}
__device__ __forceinline__ void mma16(float* c, const unsigned* a, unsigned b0, unsigned b1) {
    asm volatile("mma.sync.aligned.m16n8k16.row.col.f32.bf16.bf16.f32 "
        "{%0,%1,%2,%3}, {%4,%5,%6,%7}, {%8,%9}, {%0,%1,%2,%3};"
        : "+f"(c[0]), "+f"(c[1]), "+f"(c[2]), "+f"(c[3])
        : "r"(a[0]), "r"(a[1]), "r"(a[2]), "r"(a[3]), "r"(b0), "r"(b1));
}
__device__ __forceinline__ void cp16(unsigned dst, const void* src, int sz) {
    asm volatile("cp.async.cg.shared.global [%0], [%1], 16, %2;"
        :: "r"(dst), "l"(src), "r"(sz) : "memory");
}

// ---------------- weight tf32 pre-round ----------------
__global__ __launch_bounds__(256) void round_kernel(const float* __restrict__ in,
                                                    float* __restrict__ out, int n)
{
    int i = blockIdx.x * 256 + threadIdx.x;
    if (i < n) out[i] = tfround(in[i]);
}

// ---------------- LayerNorm ----------------
__global__ __launch_bounds__(256) void ln_kernel(const float* __restrict__ in,
    const float* __restrict__ gamma, const float* __restrict__ beta,
    float* __restrict__ out, float* __restrict__ outr)
{
    int t = blockIdx.x;
    const float* row = in + (size_t)t * CC;
    float s = 0.f, s2 = 0.f;
    for (int i = threadIdx.x; i < CC; i += 256) { float v = row[i]; s += v; s2 += v * v; }
    __shared__ float sh[64];
    #pragma unroll
    for (int o = 16; o > 0; o >>= 1) { s += __shfl_xor_sync(~0u, s, o); s2 += __shfl_xor_sync(~0u, s2, o); }
    int w = threadIdx.x >> 5, l = threadIdx.x & 31;
    if (l == 0) { sh[w] = s; sh[32 + w] = s2; }
    __syncthreads();
    if (threadIdx.x == 0) {
        float a = 0.f, b = 0.f;
        #pragma unroll
        for (int i = 0; i < 8; i++) { a += sh[i]; b += sh[32 + i]; }
        sh[0] = a; sh[1] = b;
    }
    __syncthreads();
    float mean = sh[0] * (1.f / CC);
    float var  = sh[1] * (1.f / CC) - mean * mean;
    float rstd = rsqrtf(var + 1e-5f);
    for (int i = threadIdx.x; i < CC; i += 256) {
        float v = (row[i] - mean) * rstd * gamma[i] + beta[i];
        if (out)  out[(size_t)t * CC + i] = v;
        if (outr) outr[(size_t)t * CC + i] = tfround(v);
    }
}

// ---------------- combine: out += buf0 + buf1 ----------------
__global__ __launch_bounds__(256) void moe_combine_kernel(float* __restrict__ out)
{
    size_t i = ((size_t)blockIdx.x * 256 + threadIdx.x) * 4;
    float4 a = *(const float4*)&g_moebuf[0][i];
    float4 b = *(const float4*)&g_moebuf[1][i];
    float4 o = *(const float4*)&out[i];
    o.x += a.x + b.x; o.y += a.y + b.y; o.z += a.z + b.z; o.w += a.w + b.w;
    *(float4*)&out[i] = o;
}

// ---------------- TF32 GEMM, 4-stage cp.async pipeline, 128x128x16 ----------------
// MODE 0: C=A@B +bias+resid   MODE 1: MoE gather -> slot-buffer stores   MODE 2: QKV -> bf16 q/k/vt
#define BM 128
#define BN 128
#define GBK 16
#define GS 4
#define AW 20
#define BWW 136
#define GEMM_SMEM ((GS*BM*AW + GS*GBK*BWW + 384) * 4)

template<int MODE>
__global__ __launch_bounds__(256, 2) void tf32_gemm_kernel(
    const float* __restrict__ A, const float* __restrict__ Bm, float* __restrict__ Cm,
    int Nn, int K,
    const float* __restrict__ bias, const float* __restrict__ resid,
    __nv_bfloat16* __restrict__ qb, __nv_bfloat16* __restrict__ kb,
    __nv_bfloat16* __restrict__ vtb)
{
    extern __shared__ float gsm[];
    float* As = gsm;
    float* Bs = As + GS * BM * AW;
    int*   stok = (int*)(Bs + GS * GBK * BWW);
    float* swt  = (float*)(stok + BM);
    int*   sslot = (int*)(swt + BM);

    int bm = blockIdx.y * BM, bn = blockIdx.x * BN;
    int tid = threadIdx.x;
    int e = 0;
    if (MODE == 1) {
        e = blockIdx.z;
        int cnt = g_cnt[e];
        if (bm >= cnt) return;
        if (tid < BM) {
            int m = bm + tid;
            if (m < cnt) {
                stok[tid] = g_list[e * TT + m];
                swt[tid]  = g_wt[e * TT + m];
                sslot[tid] = g_slot[e * TT + m];
            } else { stok[tid] = -1; swt[tid] = 0.f; sslot[tid] = 0; }
        }
        __syncthreads();
    }

    const float* Bbase = (MODE == 1) ? (Bm + (size_t)e * K * Nn) : Bm;
    unsigned a_smem = (unsigned)__cvta_generic_to_shared(As);
    unsigned b_smem = (unsigned)__cvta_generic_to_shared(Bs);

    int aRow0 = tid >> 1;
    int aSeg0 = (tid & 1) * 2;

    auto fill_stage = [&](int s, int k0) {
        #pragma unroll
        for (int j = 0; j < 2; j++) {
            int row = aRow0, seg = aSeg0 + j;
            const float* src;
            int sz = 16;
            if (MODE == 1) {
                int tok = stok[row];
                if (tok >= 0) src = A + (size_t)tok * K + k0 + seg * 4;
                else { src = A; sz = 0; }
            } else {
                src = A + (size_t)(bm + row) * K + k0 + seg * 4;
            }
            unsigned dst = a_smem + (unsigned)((s * BM * AW + row * AW + seg * 4) * 4);
            cp16(dst, src, sz);
        }
        #pragma unroll
        for (int j = 0; j < 2; j++) {
            int chunk = tid + j * 256;
            int krow = chunk >> 5, seg = chunk & 31;
            const float* src = Bbase + (size_t)(k0 + krow) * Nn + bn + seg * 4;
            unsigned dst = b_smem + (unsigned)((s * GBK * BWW + krow * BWW + seg * 4) * 4);
            cp16(dst, src, 16);
        }
    };

    #pragma unroll
    for (int s = 0; s < GS - 1; s++) {
        fill_stage(s, s * GBK);
        asm volatile("cp.async.commit_group;" ::: "memory");
    }

    int lane = tid & 31, wid = tid >> 5;
    int wm = (wid & 3) * 32;
    int wn = (wid >> 2) * 64;
    int g = lane >> 2, c = lane & 3;

    float acc[2][8][4];
    #pragma unroll
    for (int mi = 0; mi < 2; mi++)
        #pragma unroll
        for (int ni = 0; ni < 8; ni++)
            #pragma unroll
            for (int q = 0; q < 4; q++) acc[mi][ni][q] = 0.f;

    int nIter = K / GBK;
    for (int it = 0; it < nIter; it++) {
        asm volatile("cp.async.wait_group 2;" ::: "memory");
        __syncthreads();

        int nx = it + GS - 1;
        if (nx < nIter) fill_stage(nx & (GS - 1), nx * GBK);
        asm volatile("cp.async.commit_group;" ::: "memory");

        const float* Ab = As + (it & (GS - 1)) * BM * AW;
        const float* Bb = Bs + (it & (GS - 1)) * GBK * BWW;
        #pragma unroll
        for (int kk = 0; kk < GBK; kk += 8) {
            unsigned af[2][4];
            #pragma unroll
            for (int mi = 0; mi < 2; mi++) {
                int r0 = wm + mi * 16 + g;
                af[mi][0] = __float_as_uint(Ab[r0 * AW + kk + c]);
                af[mi][1] = __float_as_uint(Ab[(r0 + 8) * AW + kk + c]);
                af[mi][2] = __float_as_uint(Ab[r0 * AW + kk + c + 4]);
                af[mi][3] = __float_as_uint(Ab[(r0 + 8) * AW + kk + c + 4]);
            }
            #pragma unroll
            for (int ni = 0; ni < 8; ni++) {
                unsigned bf[2];
                bf[0] = __float_as_uint(Bb[(kk + c) * BWW + wn + ni * 8 + g]);
                bf[1] = __float_as_uint(Bb[(kk + c + 4) * BWW + wn + ni * 8 + g]);
                mma8(acc[0][ni], af[0], bf);
                mma8(acc[1][ni], af[1], bf);
            }
        }
    }

    #pragma unroll
    for (int mi = 0; mi < 2; mi++) {
        int rl0 = wm + mi * 16 + g;
        int rl1 = rl0 + 8;
        if (MODE == 1) {
            int tk0 = stok[rl0], tk1 = stok[rl1];
            float w0 = swt[rl0], w1 = swt[rl1];
            float* base0 = (tk0 >= 0) ? &g_moebuf[sslot[rl0]][(size_t)tk0 * Nn] : nullptr;
            float* base1 = (tk1 >= 0) ? &g_moebuf[sslot[rl1]][(size_t)tk1 * Nn] : nullptr;
            #pragma unroll
            for (int ni = 0; ni < 8; ni++) {
                int cn = bn + wn + ni * 8 + 2 * c;
                float b0 = bias[(size_t)e * Nn + cn], b1 = bias[(size_t)e * Nn + cn + 1];
                if (base0)
                    *(float2*)(base0 + cn) = make_float2(w0 * (acc[mi][ni][0] + b0),
                                                         w0 * (acc[mi][ni][1] + b1));
                if (base1)
                    *(float2*)(base1 + cn) = make_float2(w1 * (acc[mi][ni][2] + b0),
                                                         w1 * (acc[mi][ni][3] + b1));
            }
        } else if (MODE == 2) {
            int r0 = bm + rl0, r1 = bm + rl1;
            int b0r = r0 >> 10, n0 = r0 & 1023;
            int b1r = r1 >> 10, n1 = r1 & 1023;
            #pragma unroll
            for (int ni = 0; ni < 8; ni++) {
                int cn = bn + wn + ni * 8 + 2 * c;
                int sect = cn / CC;
                int cc = cn - sect * CC;
                int h = cc >> 6, d = cc & 63;
                if (sect == 0) {
                    size_t i0 = ((size_t)(b0r * HH + h) * NN + n0) * DH + d;
                    size_t i1 = ((size_t)(b1r * HH + h) * NN + n1) * DH + d;
                    *(unsigned*)&qb[i0] = f2bf2(acc[mi][ni][0] * 0.125f, acc[mi][ni][1] * 0.125f);
                    *(unsigned*)&qb[i1] = f2bf2(acc[mi][ni][2] * 0.125f, acc[mi][ni][3] * 0.125f);
                } else if (sect == 1) {
                    size_t i0 = ((size_t)(b0r * HH + h) * NN + n0) * DH + d;
                    size_t i1 = ((size_t)(b1r * HH + h) * NN + n1) * DH + d;
                    *(unsigned*)&kb[i0] = f2bf2(acc[mi][ni][0], acc[mi][ni][1]);
                    *(unsigned*)&kb[i1] = f2bf2(acc[mi][ni][2], acc[mi][ni][3]);
                } else {
                    size_t base0 = (size_t)(b0r * HH + h) * DH;
                    size_t base1 = (size_t)(b1r * HH + h) * DH;
                    vtb[(base0 + d) * NN + n0]     = __float2bfloat16_rn(acc[mi][ni][0]);
                    vtb[(base0 + d + 1) * NN + n0] = __float2bfloat16_rn(acc[mi][ni][1]);
                    vtb[(base1 + d) * NN + n1]     = __float2bfloat16_rn(acc[mi][ni][2]);
                    vtb[(base1 + d + 1) * NN + n1] = __float2bfloat16_rn(acc[mi][ni][3]);
                }
            }
        } else {
            int r0 = bm + rl0, r1 = bm + rl1;
            #pragma unroll
            for (int ni = 0; ni < 8; ni++) {
                int cn = bn + wn + ni * 8 + 2 * c;
                float2 v0 = make_float2(acc[mi][ni][0], acc[mi][ni][1]);
                float2 v1 = make_float2(acc[mi][ni][2], acc[mi][ni][3]);
                if (bias) {
                    float b0 = bias[cn], b1 = bias[cn + 1];
                    v0.x += b0; v0.y += b1; v1.x += b0; v1.y += b1;
                }
                if (resid) {
                    float2 r0v = *(const float2*)(resid + (size_t)r0 * Nn + cn);
                    float2 r1v = *(const float2*)(resid + (size_t)r1 * Nn + cn);
                    v0.x += r0v.x; v0.y += r0v.y; v1.x += r1v.x; v1.y += r1v.y;
                }
                *(float2*)(Cm + (size_t)r0 * Nn + cn) = v0;
                *(float2*)(Cm + (size_t)r1 * Nn + cn) = v1;
            }
        }
    }
}

// ---------------- bf16 flash attention ----------------
#define QSTRW 36
#define KSTRW 36
#define ATTN_SMEM ((128*QSTRW + 2*64*KSTRW + 2*64*KSTRW) * 4)

__global__ __launch_bounds__(256, 2) void attn_bf16_kernel(
    const __nv_bfloat16* __restrict__ qb,
    const __nv_bfloat16* __restrict__ kb,
    const __nv_bfloat16* __restrict__ vt,
    float* __restrict__ o)
{
    extern __shared__ unsigned smem_u[];
    unsigned* QPs = smem_u;
    unsigned* Ks  = QPs + 128 * QSTRW;
    unsigned* Vs  = Ks + 2 * 64 * KSTRW;

    int bh = blockIdx.y;
    int bb = bh / HH, hh = bh % HH;
    int q0 = blockIdx.x * 128;
    int tid = threadIdx.x;
    int lane = tid & 31, wid = tid >> 5;
    int wm = wid * 16;
    int g = lane >> 2, c = lane & 3;

    const __nv_bfloat16* q_head = qb + ((size_t)(bb * HH + hh) * NN + q0) * DH;
    const __nv_bfloat16* k_head = kb + (size_t)(bb * HH + hh) * NN * DH;
    const __nv_bfloat16* v_head = vt + (size_t)(bb * HH + hh) * DH * NN;

    {
        int row = tid >> 1, seg = tid & 1;
        const uint4* src = (const uint4*)(q_head + (size_t)row * DH + seg * 32);
        unsigned* dst = QPs + row * QSTRW + seg * 16;
        #pragma unroll
        for (int i = 0; i < 4; i++)
            *(uint4*)(dst + i * 4) = src[i];
    }
    __syncthreads();

    unsigned qf[4][4];
    #pragma unroll
    for (int kc = 0; kc < 4; kc++) {
        int bw = kc * 8 + c;
        qf[kc][0] = QPs[(wm + g) * QSTRW + bw];
        qf[kc][1] = QPs[(wm + g + 8) * QSTRW + bw];
        qf[kc][2] = QPs[(wm + g) * QSTRW + bw + 4];
        qf[kc][3] = QPs[(wm + g + 8) * QSTRW + bw + 4];
    }
    __syncthreads();

    float oacc[8][4];
    #pragma unroll
    for (int ni = 0; ni < 8; ni++)
        #pragma unroll
        for (int q = 0; q < 4; q++) oacc[ni][q] = 0.f;
    float m0 = -1e30f, m1 = -1e30f, l0 = 0.f, l1 = 0.f;

    int ktok = tid & 63, kseg = tid >> 6;
    int vd = tid & 63, vseg = tid >> 6;

    {
        const uint4* ksrc = (const uint4*)(k_head + (size_t)ktok * DH);
        *(uint4*)(Ks + ktok * KSTRW + kseg * 4) = ksrc[kseg];
        *(uint4*)(Ks + ktok * KSTRW + (kseg + 4) * 4) = ksrc[kseg + 4];
        const __nv_bfloat16* vrow = v_head + (size_t)vd * NN;
        *(uint4*)(Vs + vd * KSTRW + vseg * 4)       = *(const uint4*)(vrow + vseg * 8);
        *(uint4*)(Vs + vd * KSTRW + (vseg + 4) * 4) = *(const uint4*)(vrow + (vseg + 4) * 8);
    }
    __syncthreads();

    const int NTILES = NN / 64;
    for (int tile = 0; tile < NTILES; tile++) {
        int cur = tile & 1, nxt = cur ^ 1;
        const unsigned* Kb = Ks + cur * 64 * KSTRW;
        const unsigned* Vb = Vs + cur * 64 * KSTRW;
        bool more = (tile + 1 < NTILES);

        uint4 kx0, kx1, vx0, vx1;
        if (more) {
            const uint4* ksrc = (const uint4*)(k_head + (size_t)(tile + 1) * 64 * DH + (size_t)ktok * DH);
            kx0 = ksrc[kseg]; kx1 = ksrc[kseg + 4];
            const __nv_bfloat16* vrow = v_head + (size_t)vd * NN + (tile + 1) * 64;
            vx0 = *(const uint4*)(vrow + vseg * 8);
            vx1 = *(const uint4*)(vrow + (vseg + 4) * 8);
        }

        float sa[8][4];
        #pragma unroll
        for (int ni = 0; ni < 8; ni++)
            #pragma unroll
            for (int q = 0; q < 4; q++) sa[ni][q] = 0.f;
        #pragma unroll
        for (int kc = 0; kc < 4; kc++) {
            #pragma unroll
            for (int ni = 0; ni < 8; ni++) {
                int bw = (ni * 8 + g) * KSTRW + kc * 8 + c;
                mma16(sa[ni], qf[kc], Kb[bw], Kb[bw + 4]);
            }
        }

        float mx0 = -1e30f, mx1 = -1e30f;
        #pragma unroll
        for (int ni = 0; ni < 8; ni++) {
            mx0 = fmaxf(mx0, fmaxf(sa[ni][0], sa[ni][1]));
            mx1 = fmaxf(mx1, fmaxf(sa[ni][2], sa[ni][3]));
        }
        mx0 = fmaxf(mx0, __shfl_xor_sync(~0u, mx0, 1));
        mx0 = fmaxf(mx0, __shfl_xor_sync(~0u, mx0, 2));
        mx1 = fmaxf(mx1, __shfl_xor_sync(~0u, mx1, 1));
        mx1 = fmaxf(mx1, __shfl_xor_sync(~0u, mx1, 2));
        float mn0 = fmaxf(m0, mx0), mn1 = fmaxf(m1, mx1);
        float al0 = __expf(m0 - mn0), al1 = __expf(m1 - mn1);
        float sum0 = 0.f, sum1 = 0.f;
        #pragma unroll
        for (int ni = 0; ni < 8; ni++) {
            float p00 = __expf(sa[ni][0] - mn0);
            float p01 = __expf(sa[ni][1] - mn0);
            float p10 = __expf(sa[ni][2] - mn1);
            float p11 = __expf(sa[ni][3] - mn1);
            sum0 += p00 + p01; sum1 += p10 + p11;
            QPs[(wm + g) * QSTRW + ni * 4 + c]     = f2bf2(p00, p01);
            QPs[(wm + g + 8) * QSTRW + ni * 4 + c] = f2bf2(p10, p11);
        }
        sum0 += __shfl_xor_sync(~0u, sum0, 1);
        sum0 += __shfl_xor_sync(~0u, sum0, 2);
        sum1 += __shfl_xor_sync(~0u, sum1, 1);
        sum1 += __shfl_xor_sync(~0u, sum1, 2);
        l0 = l0 * al0 + sum0; l1 = l1 * al1 + sum1;
        m0 = mn0; m1 = mn1;
        #pragma unroll
        for (int ni = 0; ni < 8; ni++) {
            oacc[ni][0] *= al0; oacc[ni][1] *= al0;
            oacc[ni][2] *= al1; oacc[ni][3] *= al1;
        }
        __syncwarp();

        if (more) {
            unsigned* Kn = Ks + nxt * 64 * KSTRW;
            *(uint4*)(Kn + ktok * KSTRW + kseg * 4) = kx0;
            *(uint4*)(Kn + ktok * KSTRW + (kseg + 4) * 4) = kx1;
        }

        #pragma unroll
        for (int kc = 0; kc < 4; kc++) {
            unsigned af[4];
            int bw = kc * 8 + c;
            af[0] = QPs[(wm + g) * QSTRW + bw];
            af[1] = QPs[(wm + g + 8) * QSTRW + bw];
            af[2] = QPs[(wm + g) * QSTRW + bw + 4];
            af[3] = QPs[(wm + g + 8) * QSTRW + bw + 4];
            #pragma unroll
            for (int ni = 0; ni < 8; ni++) {
                int vw = (ni * 8 + g) * KSTRW + kc * 8 + c;
                mma16(oacc[ni], af, Vb[vw], Vb[vw + 4]);
            }
        }

        if (more) {
            unsigned* Vn = Vs + nxt * 64 * KSTRW;
            *(uint4*)(Vn + vd * KSTRW + vseg * 4) = vx0;
            *(uint4*)(Vn + vd * KSTRW + (vseg + 4) * 4) = vx1;
        }
        __syncthreads();
    }

    float inv0 = 1.f / l0, inv1 = 1.f / l1;
    size_t t0 = (size_t)bb * NN + q0 + wm + g;
    size_t t1 = t0 + 8;
    #pragma unroll
    for (int ni = 0; ni < 8; ni++) {
        int dcol = hh * DH + ni * 8 + 2 * c;
        *(float2*)&o[t0 * CC + dcol] = make_float2(tfround(oacc[ni][0] * inv0), tfround(oacc[ni][1] * inv0));
        *(float2*)&o[t1 * CC + dcol] = make_float2(tfround(oacc[ni][2] * inv1), tfround(oacc[ni][3] * inv1));
    }
}

// ---------------- router ----------------
__global__ __launch_bounds__(256) void route_kernel(
    const float* __restrict__ h2, const float* __restrict__ route_w,
    const float* __restrict__ route_b, const float* __restrict__ rln_g,
    const float* __restrict__ rln_b, const float* __restrict__ noise)
{
    int warp = threadIdx.x >> 5, lane = threadIdx.x & 31;
    int t = blockIdx.x * 8 + warp;
    const float* hrow = h2 + (size_t)t * CC;
    float acc[EE];
    #pragma unroll
    for (int e = 0; e < EE; e++) acc[e] = 0.f;
    for (int c = lane; c < CC; c += 32) {
        float hv = hrow[c];
        const float* rw = route_w + (size_t)c * EE;
        #pragma unroll
        for (int e = 0; e < EE; e++) acc[e] += hv * rw[e];
    }
    #pragma unroll
    for (int e = 0; e < EE; e++)
        #pragma unroll
        for (int off = 16; off > 0; off >>= 1)
            acc[e] += __shfl_xor_sync(~0u, acc[e], off);

    if (lane == 0) {
        float lg[EE];
        float mean = 0.f;
        #pragma unroll
        for (int e = 0; e < EE; e++) { lg[e] = acc[e] + route_b[e]; mean += lg[e]; }
        mean *= (1.f / EE);
        float var = 0.f;
        #pragma unroll
        for (int e = 0; e < EE; e++) { float d = lg[e] - mean; var += d * d; }
        var *= (1.f / EE);
        float rstd = rsqrtf(var + 1e-5f);
        float mx = -1e30f;
        #pragma unroll
        for (int e = 0; e < EE; e++) { lg[e] = (lg[e] - mean) * rstd * rln_g[e] + rln_b[e]; mx = fmaxf(mx, lg[e]); }
        float den = 0.f;
        float r[EE];
        #pragma unroll
        for (int e = 0; e < EE; e++) { r[e] = __expf(lg[e] - mx); den += r[e]; }
        float inv = 1.f / den;
        const float* nrow = noise + (size_t)t * EE;
        #pragma unroll
        for (int e = 0; e < EE; e++) r[e] = r[e] * inv + nrow[e] * 0.125f;

        int i1 = 0;
        #pragma unroll
        for (int e = 1; e < EE; e++) if (r[e] > r[i1]) i1 = e;
        int i2 = (i1 == 0) ? 1 : 0;
        #pragma unroll
        for (int e = 0; e < EE; e++) if (e != i1 && r[e] > r[i2]) i2 = e;

        float vm = fmaxf(r[i1], r[i2]);
        float e1 = __expf(r[i1] - vm), e2 = __expf(r[i2] - vm);
        float wsum = 1.f / (e1 + e2);
        float w1 = e1 * wsum, w2 = e2 * wsum;

        int p1 = atomicAdd(&g_cnt[i1], 1);
        g_list[i1 * TT + p1] = t; g_wt[i1 * TT + p1] = w1; g_slot[i1 * TT + p1] = 0;
        int p2 = atomicAdd(&g_cnt[i2], 1);
        g_list[i2 * TT + p2] = t; g_wt[i2 * TT + p2] = w2; g_slot[i2 * TT + p2] = 1;
    }
}

__global__ void zero_cnt_kernel() { if (threadIdx.x < EE) g_cnt[threadIdx.x] = 0; }

// ---------------- launch ----------------
extern "C" void kernel_launch(void* const* d_in, const int* in_sizes, int n_in,
                              void* d_out, int out_size)
{
    const float* x       = (const float*)d_in[0];
    const float* noise   = (const float*)d_in[1];
    const float* ln1_g   = (const float*)d_in[2];
    const float* ln1_b   = (const float*)d_in[3];
    const float* qkv_w   = (const float*)d_in[4];
    const float* proj_w  = (const float*)d_in[5];
    const float* proj_b  = (const float*)d_in[6];
    const float* ln2_g   = (const float*)d_in[7];
    const float* ln2_b   = (const float*)d_in[8];
    const float* route_w = (const float*)d_in[9];
    const float* route_b = (const float*)d_in[10];
    const float* rln_g   = (const float*)d_in[11];
    const float* rln_b   = (const float*)d_in[12];
    const float* exp_w   = (const float*)d_in[13];
    const float* exp_b   = (const float*)d_in[14];
    float* out = (float*)d_out;

    float *h1, *o, *h2, *h2r, *qkvwr, *projwr, *expwr;
    __nv_bfloat16 *qbp, *kbp, *vtp;
    cudaGetSymbolAddress((void**)&h1,  g_h1);
    cudaGetSymbolAddress((void**)&o,   g_o);
    cudaGetSymbolAddress((void**)&h2,  g_h2);
    cudaGetSymbolAddress((void**)&h2r, g_h2r);
    cudaGetSymbolAddress((void**)&qkvwr,  g_qkvwr);
    cudaGetSymbolAddress((void**)&projwr, g_projwr);
    cudaGetSymbolAddress((void**)&expwr,  g_expwr);
    cudaGetSymbolAddress((void**)&qbp, g_qb);
    cudaGetSymbolAddress((void**)&kbp, g_kb);
    cudaGetSymbolAddress((void**)&vtp, g_vt);

    cudaFuncSetAttribute(attn_bf16_kernel, cudaFuncAttributeMaxDynamicSharedMemorySize, (int)ATTN_SMEM);
    cudaFuncSetAttribute(tf32_gemm_kernel<0>, cudaFuncAttributeMaxDynamicSharedMemorySize, (int)GEMM_SMEM);
    cudaFuncSetAttribute(tf32_gemm_kernel<1>, cudaFuncAttributeMaxDynamicSharedMemorySize, (int)GEMM_SMEM);
    cudaFuncSetAttribute(tf32_gemm_kernel<2>, cudaFuncAttributeMaxDynamicSharedMemorySize, (int)GEMM_SMEM);

    // 0) pre-round weights to tf32
    round_kernel<<<(CC * 3 * CC) / 256, 256>>>(qkv_w, qkvwr, CC * 3 * CC);
    round_kernel<<<(CC * CC) / 256, 256>>>(proj_w, projwr, CC * CC);
    round_kernel<<<(EE * CC * CC) / 256, 256>>>(exp_w, expwr, EE * CC * CC);
    // 1) LN1 -> rounded h1
    ln_kernel<<<TT, 256>>>(x, ln1_g, ln1_b, nullptr, h1);
    // 2) QKV GEMM (tf32) -> bf16 q/k/vt
    tf32_gemm_kernel<2><<<dim3(3 * CC / BN, TT / BM), 256, GEMM_SMEM>>>(
        h1, qkvwr, nullptr, 3 * CC, CC, nullptr, nullptr, qbp, kbp, vtp);
    // 3) attention -> rounded o
    attn_bf16_kernel<<<dim3(NN / 128, BB * HH), 256, ATTN_SMEM>>>(qbp, kbp, vtp, o);
    // 4) proj + bias + residual -> d_out
    tf32_gemm_kernel<0><<<dim3(CC / BN, TT / BM), 256, GEMM_SMEM>>>(
        o, projwr, out, CC, CC, proj_b, x, nullptr, nullptr, nullptr);
    // 5) LN2 -> full h2 (router) + rounded h2r (MoE)
    ln_kernel<<<TT, 256>>>(out, ln2_g, ln2_b, h2, h2r);
    // 6) routing
    zero_cnt_kernel<<<1, 32>>>();
    route_kernel<<<TT / 8, 256>>>(h2, route_w, route_b, rln_g, rln_b, noise);
    // 7) MoE grouped GEMM -> slot buffers (plain stores)
    tf32_gemm_kernel<1><<<dim3(CC / BN, TT / BM, EE), 256, GEMM_SMEM>>>(
        h2r, expwr, nullptr, CC, CC, exp_b, nullptr, nullptr, nullptr, nullptr);
    // 8) combine: out += buf0 + buf1
    moe_combine_kernel<<<(TT * CC / 4) / 256, 256>>>(out);
}

// round 13
// speedup vs baseline: 1.3507x; 1.3507x over previous
#include <cuda_runtime.h>
#include <cuda_bf16.h>
#include <cuda_fp16.h>
#include <math.h>
#include <stdint.h>

#define BB 16
#define NN 1024
#define CC 768
#define HH 12
#define DH 64
#define EE 8
#define TT (BB*NN)

// ---------------- scratch (no allocations allowed) ----------------
__device__ __half g_h1h[(size_t)TT * CC];            // LN1 output (fp16)
__device__ __nv_bfloat16 g_qb[(size_t)TT * CC];      // Q  [b][h][n][d]  (pre-scaled)
__device__ __nv_bfloat16 g_kb[(size_t)TT * CC];      // K  [b][h][n][d]
__device__ __nv_bfloat16 g_vt[(size_t)TT * CC];      // V  [b][h][d][n]  (transposed)
__device__ __half g_oh[(size_t)TT * CC];             // attention output (fp16)
__device__ float g_h2[(size_t)TT * CC];              // LN2 output (fp32, router)
__device__ __half g_h2h[(size_t)TT * CC];            // LN2 output (fp16, MoE A)
__device__ __half g_qkvwT[(size_t)3 * CC * CC];      // fp16 transposed weights [n][k]
__device__ __half g_projwT[(size_t)CC * CC];
__device__ __half g_expwT[(size_t)EE * CC * CC];
__device__ int   g_cnt[EE];
__device__ int   g_list[EE * TT];
__device__ float g_wt[EE * TT];

// ---------------- helpers ----------------
__device__ __forceinline__ unsigned f2bf2(float lo, float hi) {
    __nv_bfloat162 h = __floats2bfloat162_rn(lo, hi);
    return *reinterpret_cast<unsigned*>(&h);
}
// bf16 mma (attention)
__device__ __forceinline__ void mma16(float* c, const unsigned* a, unsigned b0, unsigned b1) {
    asm volatile("mma.sync.aligned.m16n8k16.row.col.f32.bf16.bf16.f32 "
        "{%0,%1,%2,%3}, {%4,%5,%6,%7}, {%8,%9}, {%0,%1,%2,%3};"
        : "+f"(c[0]), "+f"(c[1]), "+f"(c[2]), "+f"(c[3])
        : "r"(a[0]), "r"(a[1]), "r"(a[2]), "r"(a[3]), "r"(b0), "r"(b1));
}
// fp16 mma (GEMMs)
__device__ __forceinline__ void mma16h(float* c, const unsigned* a, unsigned b0, unsigned b1) {
    asm volatile("mma.sync.aligned.m16n8k16.row.col.f32.f16.f16.f32 "
        "{%0,%1,%2,%3}, {%4,%5,%6,%7}, {%8,%9}, {%0,%1,%2,%3};"
        : "+f"(c[0]), "+f"(c[1]), "+f"(c[2]), "+f"(c[3])
        : "r"(a[0]), "r"(a[1]), "r"(a[2]), "r"(a[3]), "r"(b0), "r"(b1));
}
__device__ __forceinline__ void cp16(unsigned dst, const void* src, int sz) {
    asm volatile("cp.async.cg.shared.global [%0], [%1], 16, %2;"
        :: "r"(dst), "l"(src), "r"(sz) : "memory");
}

// ---------------- weight transpose -> fp16 [n][k] ----------------
__global__ __launch_bounds__(256) void transpose_half_kernel(
    const float* __restrict__ in, __half* __restrict__ out, int R, int Cc)
{
    __shared__ float t[32][33];
    int bx = blockIdx.x * 32, by = blockIdx.y * 32;
    size_t base = (size_t)blockIdx.z * R * Cc;
    int tx = threadIdx.x & 31, ty = threadIdx.x >> 5;
    #pragma unroll
    for (int j = 0; j < 4; j++)
        t[ty + j * 8][tx] = in[base + (size_t)(by + ty + j * 8) * Cc + bx + tx];
    __syncthreads();
    #pragma unroll
    for (int j = 0; j < 4; j++)
        out[base + (size_t)(bx + ty + j * 8) * R + by + tx] = __float2half_rn(t[tx][ty + j * 8]);
}

// ---------------- LayerNorm (fp32 + fp16 outputs) ----------------
__global__ __launch_bounds__(256) void ln_kernel(const float* __restrict__ in,
    const float* __restrict__ gamma, const float* __restrict__ beta,
    float* __restrict__ out, __half* __restrict__ outh)
{
    int t = blockIdx.x;
    const float* row = in + (size_t)t * CC;
    float s = 0.f, s2 = 0.f;
    for (int i = threadIdx.x; i < CC; i += 256) { float v = row[i]; s += v; s2 += v * v; }
    __shared__ float sh[64];
    #pragma unroll
    for (int o = 16; o > 0; o >>= 1) { s += __shfl_xor_sync(~0u, s, o); s2 += __shfl_xor_sync(~0u, s2, o); }
    int w = threadIdx.x >> 5, l = threadIdx.x & 31;
    if (l == 0) { sh[w] = s; sh[32 + w] = s2; }
    __syncthreads();
    if (threadIdx.x == 0) {
        float a = 0.f, b = 0.f;
        #pragma unroll
        for (int i = 0; i < 8; i++) { a += sh[i]; b += sh[32 + i]; }
        sh[0] = a; sh[1] = b;
    }
    __syncthreads();
    float mean = sh[0] * (1.f / CC);
    float var  = sh[1] * (1.f / CC) - mean * mean;
    float rstd = rsqrtf(var + 1e-5f);
    for (int i = threadIdx.x; i < CC; i += 256) {
        float v = (row[i] - mean) * rstd * gamma[i] + beta[i];
        if (out)  out[(size_t)t * CC + i] = v;
        if (outh) outh[(size_t)t * CC + i] = __float2half_rn(v);
    }
}

// ---------------- fp16 GEMM, 128x128x32, 4-stage cp.async ----------------
// A[M,K] fp16 row-major, BT[N,K] fp16 row-major.
// MODE 0: C=A@B^T +bias+resid (fp32 out)   MODE 1: MoE gather + weighted atomicAdd
// MODE 2: QKV -> bf16 q/k/vt
#define BM 128
#define BN 128
#define GS 4
#define QAW 20                     // row stride words: 16 data (32 halves) + 4 pad
#define QSTG_W (BM * QAW)
#define GEMM_SMEM ((2 * GS * QSTG_W + 384) * 4)

template<int MODE>
__global__ __launch_bounds__(256, 2) void fp16_gemm_kernel(
    const __half* __restrict__ A, const __half* __restrict__ BT, float* __restrict__ Cm,
    int Nn,
    const float* __restrict__ bias, const float* __restrict__ resid,
    __nv_bfloat16* __restrict__ qb, __nv_bfloat16* __restrict__ kb,
    __nv_bfloat16* __restrict__ vtb)
{
    extern __shared__ unsigned qsm[];
    unsigned* As = qsm;
    unsigned* Bs = As + GS * QSTG_W;
    int*   stok = (int*)(Bs + GS * QSTG_W);
    float* swt  = (float*)(stok + BM);
    const int K = CC;

    int bm = blockIdx.y * BM, bn = blockIdx.x * BN;
    int tid = threadIdx.x;
    int e = 0;
    if (MODE == 1) {
        e = blockIdx.z;
        int cnt = g_cnt[e];
        if (bm >= cnt) return;
        if (tid < BM) {
            int m = bm + tid;
            if (m < cnt) { stok[tid] = g_list[e * TT + m]; swt[tid] = g_wt[e * TT + m]; }
            else         { stok[tid] = -1; swt[tid] = 0.f; }
        }
        __syncthreads();
    }

    const __half* BTb = (MODE == 1) ? (BT + (size_t)e * K * Nn) : BT;
    unsigned a_smem = (unsigned)__cvta_generic_to_shared(As);
    unsigned b_smem = (unsigned)__cvta_generic_to_shared(Bs);

    int rowF = tid >> 1;
    int segF = (tid & 1) * 2;

    auto fill_stage = [&](int s, int k0) {
        #pragma unroll
        for (int j = 0; j < 2; j++) {
            int seg = segF + j;
            const __half* srcA;
            int sz = 16;
            if (MODE == 1) {
                int tok = stok[rowF];
                if (tok >= 0) srcA = A + (size_t)tok * K + k0 + seg * 8;
                else { srcA = A; sz = 0; }
            } else {
                srcA = A + (size_t)(bm + rowF) * K + k0 + seg * 8;
            }
            cp16(a_smem + (unsigned)((s * QSTG_W + rowF * QAW + seg * 4) * 4), srcA, sz);
            const __half* srcB = BTb + (size_t)(bn + rowF) * K + k0 + seg * 8;
            cp16(b_smem + (unsigned)((s * QSTG_W + rowF * QAW + seg * 4) * 4), srcB, 16);
        }
    };

    #pragma unroll
    for (int s = 0; s < GS - 1; s++) {
        fill_stage(s, s * 32);
        asm volatile("cp.async.commit_group;" ::: "memory");
    }

    int lane = tid & 31, wid = tid >> 5;
    int wm = (wid & 3) * 32;
    int wn = (wid >> 2) * 64;
    int g = lane >> 2, c = lane & 3;

    float acc[2][8][4];
    #pragma unroll
    for (int mi = 0; mi < 2; mi++)
        #pragma unroll
        for (int ni = 0; ni < 8; ni++)
            #pragma unroll
            for (int q = 0; q < 4; q++) acc[mi][ni][q] = 0.f;

    int nIter = K / 32;   // 24
    for (int it = 0; it < nIter; it++) {
        asm volatile("cp.async.wait_group 2;" ::: "memory");
        __syncthreads();

        int nx = it + GS - 1;
        if (nx < nIter) fill_stage(nx & (GS - 1), nx * 32);
        asm volatile("cp.async.commit_group;" ::: "memory");

        const unsigned* Ab = As + (it & (GS - 1)) * QSTG_W;
        const unsigned* Bb = Bs + (it & (GS - 1)) * QSTG_W;
        #pragma unroll
        for (int kc = 0; kc < 2; kc++) {
            unsigned af[2][4];
            #pragma unroll
            for (int mi = 0; mi < 2; mi++) {
                int r0 = wm + mi * 16 + g;
                af[mi][0] = Ab[r0 * QAW + kc * 8 + c];
                af[mi][1] = Ab[(r0 + 8) * QAW + kc * 8 + c];
                af[mi][2] = Ab[r0 * QAW + kc * 8 + c + 4];
                af[mi][3] = Ab[(r0 + 8) * QAW + kc * 8 + c + 4];
            }
            #pragma unroll
            for (int ni = 0; ni < 8; ni++) {
                int nrow = wn + ni * 8 + g;
                unsigned b0 = Bb[nrow * QAW + kc * 8 + c];
                unsigned b1 = Bb[nrow * QAW + kc * 8 + c + 4];
                mma16h(acc[0][ni], af[0], b0, b1);
                mma16h(acc[1][ni], af[1], b0, b1);
            }
        }
    }

    // ---- epilogue ----
    #pragma unroll
    for (int mi = 0; mi < 2; mi++) {
        int rl0 = wm + mi * 16 + g;
        int rl1 = rl0 + 8;
        if (MODE == 1) {
            int tk0 = stok[rl0], tk1 = stok[rl1];
            float w0 = swt[rl0], w1 = swt[rl1];
            #pragma unroll
            for (int ni = 0; ni < 8; ni++) {
                int cn = bn + wn + ni * 8 + 2 * c;
                float b0 = bias[(size_t)e * Nn + cn], b1 = bias[(size_t)e * Nn + cn + 1];
                if (tk0 >= 0) {
                    float* p = Cm + (size_t)tk0 * Nn + cn;
                    atomicAdd(p,     w0 * (acc[mi][ni][0] + b0));
                    atomicAdd(p + 1, w0 * (acc[mi][ni][1] + b1));
                }
                if (tk1 >= 0) {
                    float* p = Cm + (size_t)tk1 * Nn + cn;
                    atomicAdd(p,     w1 * (acc[mi][ni][2] + b0));
                    atomicAdd(p + 1, w1 * (acc[mi][ni][3] + b1));
                }
            }
        } else if (MODE == 2) {
            int r0 = bm + rl0, r1 = bm + rl1;
            int b0r = r0 >> 10, n0 = r0 & 1023;
            int b1r = r1 >> 10, n1 = r1 & 1023;
            #pragma unroll
            for (int ni = 0; ni < 8; ni++) {
                int cn = bn + wn + ni * 8 + 2 * c;
                int sect = cn / CC;
                int cc = cn - sect * CC;
                int h = cc >> 6, d = cc & 63;
                if (sect == 0) {
                    size_t i0 = ((size_t)(b0r * HH + h) * NN + n0) * DH + d;
                    size_t i1 = ((size_t)(b1r * HH + h) * NN + n1) * DH + d;
                    *(unsigned*)&qb[i0] = f2bf2(acc[mi][ni][0] * 0.125f, acc[mi][ni][1] * 0.125f);
                    *(unsigned*)&qb[i1] = f2bf2(acc[mi][ni][2] * 0.125f, acc[mi][ni][3] * 0.125f);
                } else if (sect == 1) {
                    size_t i0 = ((size_t)(b0r * HH + h) * NN + n0) * DH + d;
                    size_t i1 = ((size_t)(b1r * HH + h) * NN + n1) * DH + d;
                    *(unsigned*)&kb[i0] = f2bf2(acc[mi][ni][0], acc[mi][ni][1]);
                    *(unsigned*)&kb[i1] = f2bf2(acc[mi][ni][2], acc[mi][ni][3]);
                } else {
                    size_t base0 = (size_t)(b0r * HH + h) * DH;
                    size_t base1 = (size_t)(b1r * HH + h) * DH;
                    vtb[(base0 + d) * NN + n0]     = __float2bfloat16_rn(acc[mi][ni][0]);
                    vtb[(base0 + d + 1) * NN + n0] = __float2bfloat16_rn(acc[mi][ni][1]);
                    vtb[(base1 + d) * NN + n1]     = __float2bfloat16_rn(acc[mi][ni][2]);
                    vtb[(base1 + d + 1) * NN + n1] = __float2bfloat16_rn(acc[mi][ni][3]);
                }
            }
        } else {
            int r0 = bm + rl0, r1 = bm + rl1;
            #pragma unroll
            for (int ni = 0; ni < 8; ni++) {
                int cn = bn + wn + ni * 8 + 2 * c;
                float2 v0 = make_float2(acc[mi][ni][0], acc[mi][ni][1]);
                float2 v1 = make_float2(acc[mi][ni][2], acc[mi][ni][3]);
                float b0 = bias[cn], b1 = bias[cn + 1];
                v0.x += b0; v0.y += b1; v1.x += b0; v1.y += b1;
                float2 r0v = *(const float2*)(resid + (size_t)r0 * Nn + cn);
                float2 r1v = *(const float2*)(resid + (size_t)r1 * Nn + cn);
                v0.x += r0v.x; v0.y += r0v.y; v1.x += r1v.x; v1.y += r1v.y;
                *(float2*)(Cm + (size_t)r0 * Nn + cn) = v0;
                *(float2*)(Cm + (size_t)r1 * Nn + cn) = v1;
            }
        }
    }
}

// ---------------- bf16 flash attention (o -> fp16) ----------------
#define QSTRW 36
#define KSTRW 36
#define ATTN_SMEM ((128*QSTRW + 2*64*KSTRW + 2*64*KSTRW) * 4)

__global__ __launch_bounds__(256, 2) void attn_bf16_kernel(
    const __nv_bfloat16* __restrict__ qb,
    const __nv_bfloat16* __restrict__ kb,
    const __nv_bfloat16* __restrict__ vt,
    __half* __restrict__ o)
{
    extern __shared__ unsigned smem_u[];
    unsigned* QPs = smem_u;
    unsigned* Ks  = QPs + 128 * QSTRW;
    unsigned* Vs  = Ks + 2 * 64 * KSTRW;

    int bh = blockIdx.y;
    int bb = bh / HH, hh = bh % HH;
    int q0 = blockIdx.x * 128;
    int tid = threadIdx.x;
    int lane = tid & 31, wid = tid >> 5;
    int wm = wid * 16;
    int g = lane >> 2, c = lane & 3;

    const __nv_bfloat16* q_head = qb + ((size_t)(bb * HH + hh) * NN + q0) * DH;
    const __nv_bfloat16* k_head = kb + (size_t)(bb * HH + hh) * NN * DH;
    const __nv_bfloat16* v_head = vt + (size_t)(bb * HH + hh) * DH * NN;

    {
        int row = tid >> 1, seg = tid & 1;
        const uint4* src = (const uint4*)(q_head + (size_t)row * DH + seg * 32);
        unsigned* dst = QPs + row * QSTRW + seg * 16;
        #pragma unroll
        for (int i = 0; i < 4; i++)
            *(uint4*)(dst + i * 4) = src[i];
    }
    __syncthreads();

    unsigned qf[4][4];
    #pragma unroll
    for (int kc = 0; kc < 4; kc++) {
        int bw = kc * 8 + c;
        qf[kc][0] = QPs[(wm + g) * QSTRW + bw];
        qf[kc][1] = QPs[(wm + g + 8) * QSTRW + bw];
        qf[kc][2] = QPs[(wm + g) * QSTRW + bw + 4];
        qf[kc][3] = QPs[(wm + g + 8) * QSTRW + bw + 4];
    }
    __syncthreads();

    float oacc[8][4];
    #pragma unroll
    for (int ni = 0; ni < 8; ni++)
        #pragma unroll
        for (int q = 0; q < 4; q++) oacc[ni][q] = 0.f;
    float m0 = -1e30f, m1 = -1e30f, l0 = 0.f, l1 = 0.f;

    int ktok = tid & 63, kseg = tid >> 6;
    int vd = tid & 63, vseg = tid >> 6;

    {
        const uint4* ksrc = (const uint4*)(k_head + (size_t)ktok * DH);
        *(uint4*)(Ks + ktok * KSTRW + kseg * 4) = ksrc[kseg];
        *(uint4*)(Ks + ktok * KSTRW + (kseg + 4) * 4) = ksrc[kseg + 4];
        const __nv_bfloat16* vrow = v_head + (size_t)vd * NN;
        *(uint4*)(Vs + vd * KSTRW + vseg * 4)       = *(const uint4*)(vrow + vseg * 8);
        *(uint4*)(Vs + vd * KSTRW + (vseg + 4) * 4) = *(const uint4*)(vrow + (vseg + 4) * 8);
    }
    __syncthreads();

    const int NTILES = NN / 64;
    for (int tile = 0; tile < NTILES; tile++) {
        int cur = tile & 1, nxt = cur ^ 1;
        const unsigned* Kb = Ks + cur * 64 * KSTRW;
        const unsigned* Vb = Vs + cur * 64 * KSTRW;
        bool more = (tile + 1 < NTILES);

        uint4 kx0, kx1, vx0, vx1;
        if (more) {
            const uint4* ksrc = (const uint4*)(k_head + (size_t)(tile + 1) * 64 * DH + (size_t)ktok * DH);
            kx0 = ksrc[kseg]; kx1 = ksrc[kseg + 4];
            const __nv_bfloat16* vrow = v_head + (size_t)vd * NN + (tile + 1) * 64;
            vx0 = *(const uint4*)(vrow + vseg * 8);
            vx1 = *(const uint4*)(vrow + (vseg + 4) * 8);
        }

        float sa[8][4];
        #pragma unroll
        for (int ni = 0; ni < 8; ni++)
            #pragma unroll
            for (int q = 0; q < 4; q++) sa[ni][q] = 0.f;
        #pragma unroll
        for (int kc = 0; kc < 4; kc++) {
            #pragma unroll
            for (int ni = 0; ni < 8; ni++) {
                int bw = (ni * 8 + g) * KSTRW + kc * 8 + c;
                mma16(sa[ni], qf[kc], Kb[bw], Kb[bw + 4]);
            }
        }

        float mx0 = -1e30f, mx1 = -1e30f;
        #pragma unroll
        for (int ni = 0; ni < 8; ni++) {
            mx0 = fmaxf(mx0, fmaxf(sa[ni][0], sa[ni][1]));
            mx1 = fmaxf(mx1, fmaxf(sa[ni][2], sa[ni][3]));
        }
        mx0 = fmaxf(mx0, __shfl_xor_sync(~0u, mx0, 1));
        mx0 = fmaxf(mx0, __shfl_xor_sync(~0u, mx0, 2));
        mx1 = fmaxf(mx1, __shfl_xor_sync(~0u, mx1, 1));
        mx1 = fmaxf(mx1, __shfl_xor_sync(~0u, mx1, 2));
        float mn0 = fmaxf(m0, mx0), mn1 = fmaxf(m1, mx1);
        float al0 = __expf(m0 - mn0), al1 = __expf(m1 - mn1);
        float sum0 = 0.f, sum1 = 0.f;
        #pragma unroll
        for (int ni = 0; ni < 8; ni++) {
            float p00 = __expf(sa[ni][0] - mn0);
            float p01 = __expf(sa[ni][1] - mn0);
            float p10 = __expf(sa[ni][2] - mn1);
            float p11 = __expf(sa[ni][3] - mn1);
            sum0 += p00 + p01; sum1 += p10 + p11;
            QPs[(wm + g) * QSTRW + ni * 4 + c]     = f2bf2(p00, p01);
            QPs[(wm + g + 8) * QSTRW + ni * 4 + c] = f2bf2(p10, p11);
        }
        sum0 += __shfl_xor_sync(~0u, sum0, 1);
        sum0 += __shfl_xor_sync(~0u, sum0, 2);
        sum1 += __shfl_xor_sync(~0u, sum1, 1);
        sum1 += __shfl_xor_sync(~0u, sum1, 2);
        l0 = l0 * al0 + sum0; l1 = l1 * al1 + sum1;
        m0 = mn0; m1 = mn1;
        #pragma unroll
        for (int ni = 0; ni < 8; ni++) {
            oacc[ni][0] *= al0; oacc[ni][1] *= al0;
            oacc[ni][2] *= al1; oacc[ni][3] *= al1;
        }
        __syncwarp();

        if (more) {
            unsigned* Kn = Ks + nxt * 64 * KSTRW;
            *(uint4*)(Kn + ktok * KSTRW + kseg * 4) = kx0;
            *(uint4*)(Kn + ktok * KSTRW + (kseg + 4) * 4) = kx1;
        }

        #pragma unroll
        for (int kc = 0; kc < 4; kc++) {
            unsigned af[4];
            int bw = kc * 8 + c;
            af[0] = QPs[(wm + g) * QSTRW + bw];
            af[1] = QPs[(wm + g + 8) * QSTRW + bw];
            af[2] = QPs[(wm + g) * QSTRW + bw + 4];
            af[3] = QPs[(wm + g + 8) * QSTRW + bw + 4];
            #pragma unroll
            for (int ni = 0; ni < 8; ni++) {
                int vw = (ni * 8 + g) * KSTRW + kc * 8 + c;
                mma16(oacc[ni], af, Vb[vw], Vb[vw + 4]);
            }
        }

        if (more) {
            unsigned* Vn = Vs + nxt * 64 * KSTRW;
            *(uint4*)(Vn + vd * KSTRW + vseg * 4) = vx0;
            *(uint4*)(Vn + vd * KSTRW + (vseg + 4) * 4) = vx1;
        }
        __syncthreads();
    }

    float inv0 = 1.f / l0, inv1 = 1.f / l1;
    size_t t0 = (size_t)bb * NN + q0 + wm + g;
    size_t t1 = t0 + 8;
    #pragma unroll
    for (int ni = 0; ni < 8; ni++) {
        int dcol = hh * DH + ni * 8 + 2 * c;
        *(__half2*)&o[t0 * CC + dcol] = __floats2half2_rn(oacc[ni][0] * inv0, oacc[ni][1] * inv0);
        *(__half2*)&o[t1 * CC + dcol] = __floats2half2_rn(oacc[ni][2] * inv1, oacc[ni][3] * inv1);
    }
}

// ---------------- router ----------------
__global__ __launch_bounds__(256) void route_kernel(
    const float* __restrict__ h2, const float* __restrict__ route_w,
    const float* __restrict__ route_b, const float* __restrict__ rln_g,
    const float* __restrict__ rln_b, const float* __restrict__ noise)
{
    int warp = threadIdx.x >> 5, lane = threadIdx.x & 31;
    int t = blockIdx.x * 8 + warp;
    const float* hrow = h2 + (size_t)t * CC;
    float acc[EE];
    #pragma unroll
    for (int e = 0; e < EE; e++) acc[e] = 0.f;
    for (int c = lane; c < CC; c += 32) {
        float hv = hrow[c];
        const float* rw = route_w + (size_t)c * EE;
        #pragma unroll
        for (int e = 0; e < EE; e++) acc[e] += hv * rw[e];
    }
    #pragma unroll
    for (int e = 0; e < EE; e++)
        #pragma unroll
        for (int off = 16; off > 0; off >>= 1)
            acc[e] += __shfl_xor_sync(~0u, acc[e], off);

    if (lane == 0) {
        float lg[EE];
        float mean = 0.f;
        #pragma unroll
        for (int e = 0; e < EE; e++) { lg[e] = acc[e] + route_b[e]; mean += lg[e]; }
        mean *= (1.f / EE);
        float var = 0.f;
        #pragma unroll
        for (int e = 0; e < EE; e++) { float d = lg[e] - mean; var += d * d; }
        var *= (1.f / EE);
        float rstd = rsqrtf(var + 1e-5f);
        float mx = -1e30f;
        #pragma unroll
        for (int e = 0; e < EE; e++) { lg[e] = (lg[e] - mean) * rstd * rln_g[e] + rln_b[e]; mx = fmaxf(mx, lg[e]); }
        float den = 0.f;
        float r[EE];
        #pragma unroll
        for (int e = 0; e < EE; e++) { r[e] = __expf(lg[e] - mx); den += r[e]; }
        float inv = 1.f / den;
        const float* nrow = noise + (size_t)t * EE;
        #pragma unroll
        for (int e = 0; e < EE; e++) r[e] = r[e] * inv + nrow[e] * 0.125f;

        int i1 = 0;
        #pragma unroll
        for (int e = 1; e < EE; e++) if (r[e] > r[i1]) i1 = e;
        int i2 = (i1 == 0) ? 1 : 0;
        #pragma unroll
        for (int e = 0; e < EE; e++) if (e != i1 && r[e] > r[i2]) i2 = e;

        float vm = fmaxf(r[i1], r[i2]);
        float e1 = __expf(r[i1] - vm), e2 = __expf(r[i2] - vm);
        float wsum = 1.f / (e1 + e2);
        float w1 = e1 * wsum, w2 = e2 * wsum;

        int p1 = atomicAdd(&g_cnt[i1], 1);
        g_list[i1 * TT + p1] = t; g_wt[i1 * TT + p1] = w1;
        int p2 = atomicAdd(&g_cnt[i2], 1);
        g_list[i2 * TT + p2] = t; g_wt[i2 * TT + p2] = w2;
    }
}

__global__ void zero_cnt_kernel() { if (threadIdx.x < EE) g_cnt[threadIdx.x] = 0; }

// ---------------- launch ----------------
extern "C" void kernel_launch(void* const* d_in, const int* in_sizes, int n_in,
                              void* d_out, int out_size)
{
    const float* x       = (const float*)d_in[0];
    const float* noise   = (const float*)d_in[1];
    const float* ln1_g   = (const float*)d_in[2];
    const float* ln1_b   = (const float*)d_in[3];
    const float* qkv_w   = (const float*)d_in[4];
    const float* proj_w  = (const float*)d_in[5];
    const float* proj_b  = (const float*)d_in[6];
    const float* ln2_g   = (const float*)d_in[7];
    const float* ln2_b   = (const float*)d_in[8];
    const float* route_w = (const float*)d_in[9];
    const float* route_b = (const float*)d_in[10];
    const float* rln_g   = (const float*)d_in[11];
    const float* rln_b   = (const float*)d_in[12];
    const float* exp_w   = (const float*)d_in[13];
    const float* exp_b   = (const float*)d_in[14];
    float* out = (float*)d_out;

    float *h2;
    __half *h1h, *oh, *h2h, *qkvwT, *projwT, *expwT;
    __nv_bfloat16 *qbp, *kbp, *vtp;
    cudaGetSymbolAddress((void**)&h1h, g_h1h);
    cudaGetSymbolAddress((void**)&oh,  g_oh);
    cudaGetSymbolAddress((void**)&h2,  g_h2);
    cudaGetSymbolAddress((void**)&h2h, g_h2h);
    cudaGetSymbolAddress((void**)&qkvwT,  g_qkvwT);
    cudaGetSymbolAddress((void**)&projwT, g_projwT);
    cudaGetSymbolAddress((void**)&expwT,  g_expwT);
    cudaGetSymbolAddress((void**)&qbp, g_qb);
    cudaGetSymbolAddress((void**)&kbp, g_kb);
    cudaGetSymbolAddress((void**)&vtp, g_vt);

    cudaFuncSetAttribute(attn_bf16_kernel, cudaFuncAttributeMaxDynamicSharedMemorySize, (int)ATTN_SMEM);
    cudaFuncSetAttribute(fp16_gemm_kernel<0>, cudaFuncAttributeMaxDynamicSharedMemorySize, (int)GEMM_SMEM);
    cudaFuncSetAttribute(fp16_gemm_kernel<1>, cudaFuncAttributeMaxDynamicSharedMemorySize, (int)GEMM_SMEM);
    cudaFuncSetAttribute(fp16_gemm_kernel<2>, cudaFuncAttributeMaxDynamicSharedMemorySize, (int)GEMM_SMEM);

    // 0) weight transpose -> fp16 [n][k]
    transpose_half_kernel<<<dim3(3 * CC / 32, CC / 32), 256>>>(qkv_w, qkvwT, CC, 3 * CC);
    transpose_half_kernel<<<dim3(CC / 32, CC / 32), 256>>>(proj_w, projwT, CC, CC);
    transpose_half_kernel<<<dim3(CC / 32, CC / 32, EE), 256>>>(exp_w, expwT, CC, CC);
    // 1) LN1 -> fp16 h1
    ln_kernel<<<TT, 256>>>(x, ln1_g, ln1_b, nullptr, h1h);
    // 2) QKV GEMM (fp16 mma) -> bf16 q/k/vt
    fp16_gemm_kernel<2><<<dim3(3 * CC / BN, TT / BM), 256, GEMM_SMEM>>>(
        h1h, qkvwT, nullptr, 3 * CC, nullptr, nullptr, qbp, kbp, vtp);
    // 3) attention -> fp16 o
    attn_bf16_kernel<<<dim3(NN / 128, BB * HH), 256, ATTN_SMEM>>>(qbp, kbp, vtp, oh);
    // 4) proj + bias + residual -> d_out (fp16 mma, fp32 epilogue)
    fp16_gemm_kernel<0><<<dim3(CC / BN, TT / BM), 256, GEMM_SMEM>>>(
        oh, projwT, out, CC, proj_b, x, nullptr, nullptr, nullptr);
    // 5) LN2 -> fp32 h2 (router) + fp16 h2h (MoE)
    ln_kernel<<<TT, 256>>>(out, ln2_g, ln2_b, h2, h2h);
    // 6) routing
    zero_cnt_kernel<<<1, 32>>>();
    route_kernel<<<TT / 8, 256>>>(h2, route_w, route_b, rln_g, rln_b, noise);
    // 7) MoE grouped GEMM (fp16 mma), atomicAdd into d_out
    fp16_gemm_kernel<1><<<dim3(CC / BN, TT / BM, EE), 256, GEMM_SMEM>>>(
        h2h, expwT, out, CC, exp_b, nullptr, nullptr, nullptr, nullptr);
}

// round 14
// speedup vs baseline: 1.4062x; 1.0411x over previous
#include <cuda_runtime.h>
#include <cuda_bf16.h>
#include <cuda_fp16.h>
#include <math.h>
#include <stdint.h>

#define BB 16
#define NN 1024
#define CC 768
#define HH 12
#define DH 64
#define EE 8
#define TT (BB*NN)

// ---------------- scratch (no allocations allowed) ----------------
__device__ __half g_h1h[(size_t)TT * CC];            // LN1 output (fp16)
__device__ __nv_bfloat16 g_qb[(size_t)TT * CC];      // Q  [b][h][n][d]  (pre-scaled)
__device__ __nv_bfloat16 g_kb[(size_t)TT * CC];      // K  [b][h][n][d]
__device__ __nv_bfloat16 g_vt[(size_t)TT * CC];      // V  [b][h][d][n]  (transposed)
__device__ __half g_oh[(size_t)TT * CC];             // attention output (fp16)
__device__ __half g_h2h[(size_t)TT * CC];            // LN2 output (fp16, MoE A)
__device__ __half g_qkvwT[(size_t)3 * CC * CC];      // fp16 transposed weights [n][k]
__device__ __half g_projwT[(size_t)CC * CC];
__device__ __half g_expwT[(size_t)EE * CC * CC];
__device__ int   g_cnt[EE];
__device__ int   g_list[EE * TT];
__device__ float g_wt[EE * TT];

// ---------------- helpers ----------------
__device__ __forceinline__ unsigned f2bf2(float lo, float hi) {
    __nv_bfloat162 h = __floats2bfloat162_rn(lo, hi);
    return *reinterpret_cast<unsigned*>(&h);
}
__device__ __forceinline__ void mma16(float* c, const unsigned* a, unsigned b0, unsigned b1) {
    asm volatile("mma.sync.aligned.m16n8k16.row.col.f32.bf16.bf16.f32 "
        "{%0,%1,%2,%3}, {%4,%5,%6,%7}, {%8,%9}, {%0,%1,%2,%3};"
        : "+f"(c[0]), "+f"(c[1]), "+f"(c[2]), "+f"(c[3])
        : "r"(a[0]), "r"(a[1]), "r"(a[2]), "r"(a[3]), "r"(b0), "r"(b1));
}
__device__ __forceinline__ void mma16h(float* c, const unsigned* a, unsigned b0, unsigned b1) {
    asm volatile("mma.sync.aligned.m16n8k16.row.col.f32.f16.f16.f32 "
        "{%0,%1,%2,%3}, {%4,%5,%6,%7}, {%8,%9}, {%0,%1,%2,%3};"
        : "+f"(c[0]), "+f"(c[1]), "+f"(c[2]), "+f"(c[3])
        : "r"(a[0]), "r"(a[1]), "r"(a[2]), "r"(a[3]), "r"(b0), "r"(b1));
}
__device__ __forceinline__ void cp16(unsigned dst, const void* src, int sz) {
    asm volatile("cp.async.cg.shared.global [%0], [%1], 16, %2;"
        :: "r"(dst), "l"(src), "r"(sz) : "memory");
}

// ---------------- weight transpose -> fp16 [n][k] ----------------
__global__ __launch_bounds__(256) void transpose_half_kernel(
    const float* __restrict__ in, __half* __restrict__ out, int R, int Cc)
{
    __shared__ float t[32][33];
    int bx = blockIdx.x * 32, by = blockIdx.y * 32;
    size_t base = (size_t)blockIdx.z * R * Cc;
    int tx = threadIdx.x & 31, ty = threadIdx.x >> 5;
    #pragma unroll
    for (int j = 0; j < 4; j++)
        t[ty + j * 8][tx] = in[base + (size_t)(by + ty + j * 8) * Cc + bx + tx];
    __syncthreads();
    #pragma unroll
    for (int j = 0; j < 4; j++)
        out[base + (size_t)(bx + ty + j * 8) * R + by + tx] = __float2half_rn(t[tx][ty + j * 8]);
}

// ---------------- LN1: vectorized, fp16 out, 192 thr (float4/thread) ----------------
__global__ __launch_bounds__(192) void ln1_kernel(const float* __restrict__ in,
    const float* __restrict__ gamma, const float* __restrict__ beta,
    __half* __restrict__ outh)
{
    int t = blockIdx.x;
    int c = threadIdx.x * 4;
    const float* row = in + (size_t)t * CC;
    float4 v4 = *(const float4*)(row + c);
    float s = v4.x + v4.y + v4.z + v4.w;
    float s2 = v4.x * v4.x + v4.y * v4.y + v4.z * v4.z + v4.w * v4.w;
    __shared__ float sh[16];
    #pragma unroll
    for (int o = 16; o > 0; o >>= 1) { s += __shfl_xor_sync(~0u, s, o); s2 += __shfl_xor_sync(~0u, s2, o); }
    int w = threadIdx.x >> 5, l = threadIdx.x & 31;
    if (l == 0) { sh[w] = s; sh[8 + w] = s2; }
    __syncthreads();
    if (threadIdx.x == 0) {
        float a = 0.f, b = 0.f;
        #pragma unroll
        for (int i = 0; i < 6; i++) { a += sh[i]; b += sh[8 + i]; }
        sh[0] = a; sh[1] = b;
    }
    __syncthreads();
    float mean = sh[0] * (1.f / CC);
    float rstd = rsqrtf(sh[1] * (1.f / CC) - mean * mean + 1e-5f);
    float4 gv = *(const float4*)(gamma + c);
    float4 bv = *(const float4*)(beta + c);
    float o0 = (v4.x - mean) * rstd * gv.x + bv.x;
    float o1 = (v4.y - mean) * rstd * gv.y + bv.y;
    float o2 = (v4.z - mean) * rstd * gv.z + bv.z;
    float o3 = (v4.w - mean) * rstd * gv.w + bv.w;
    __half2* op = (__half2*)(outh + (size_t)t * CC + c);
    op[0] = __floats2half2_rn(o0, o1);
    op[1] = __floats2half2_rn(o2, o3);
}

// ---------------- fused LN2 + router: fp16 h2h out + top-2 routing ----------------
__global__ __launch_bounds__(192) void ln2_route_kernel(const float* __restrict__ in,
    const float* __restrict__ gamma, const float* __restrict__ beta,
    __half* __restrict__ outh,
    const float* __restrict__ route_w, const float* __restrict__ route_b,
    const float* __restrict__ rln_g, const float* __restrict__ rln_b,
    const float* __restrict__ noise)
{
    int t = blockIdx.x;
    int c = threadIdx.x * 4;
    const float* row = in + (size_t)t * CC;
    float4 v4 = *(const float4*)(row + c);
    float s = v4.x + v4.y + v4.z + v4.w;
    float s2 = v4.x * v4.x + v4.y * v4.y + v4.z * v4.z + v4.w * v4.w;
    __shared__ float sh[16];
    __shared__ float shacc[6][EE];
    #pragma unroll
    for (int o = 16; o > 0; o >>= 1) { s += __shfl_xor_sync(~0u, s, o); s2 += __shfl_xor_sync(~0u, s2, o); }
    int w = threadIdx.x >> 5, l = threadIdx.x & 31;
    if (l == 0) { sh[w] = s; sh[8 + w] = s2; }
    __syncthreads();
    if (threadIdx.x == 0) {
        float a = 0.f, b = 0.f;
        #pragma unroll
        for (int i = 0; i < 6; i++) { a += sh[i]; b += sh[8 + i]; }
        sh[0] = a; sh[1] = b;
    }
    __syncthreads();
    float mean = sh[0] * (1.f / CC);
    float rstd = rsqrtf(sh[1] * (1.f / CC) - mean * mean + 1e-5f);
    float4 gv = *(const float4*)(gamma + c);
    float4 bv = *(const float4*)(beta + c);
    float v[4];
    v[0] = (v4.x - mean) * rstd * gv.x + bv.x;
    v[1] = (v4.y - mean) * rstd * gv.y + bv.y;
    v[2] = (v4.z - mean) * rstd * gv.z + bv.z;
    v[3] = (v4.w - mean) * rstd * gv.w + bv.w;
    __half2* op = (__half2*)(outh + (size_t)t * CC + c);
    op[0] = __floats2half2_rn(v[0], v[1]);
    op[1] = __floats2half2_rn(v[2], v[3]);

    // router logits: acc[e] += v[i] * route_w[(c+i)*8+e]
    float acc[EE];
    #pragma unroll
    for (int e = 0; e < EE; e++) acc[e] = 0.f;
    #pragma unroll
    for (int i = 0; i < 4; i++) {
        const float4* rw = (const float4*)(route_w + (size_t)(c + i) * EE);
        float4 r0 = rw[0], r1 = rw[1];
        acc[0] += v[i] * r0.x; acc[1] += v[i] * r0.y;
        acc[2] += v[i] * r0.z; acc[3] += v[i] * r0.w;
        acc[4] += v[i] * r1.x; acc[5] += v[i] * r1.y;
        acc[6] += v[i] * r1.z; acc[7] += v[i] * r1.w;
    }
    #pragma unroll
    for (int e = 0; e < EE; e++)
        #pragma unroll
        for (int o = 16; o > 0; o >>= 1)
            acc[e] += __shfl_xor_sync(~0u, acc[e], o);
    if (l == 0) {
        #pragma unroll
        for (int e = 0; e < EE; e++) shacc[w][e] = acc[e];
    }
    __syncthreads();
    if (threadIdx.x == 0) {
        float lg[EE];
        float lmean = 0.f;
        #pragma unroll
        for (int e = 0; e < EE; e++) {
            float a = 0.f;
            #pragma unroll
            for (int i = 0; i < 6; i++) a += shacc[i][e];
            lg[e] = a + route_b[e];
            lmean += lg[e];
        }
        lmean *= (1.f / EE);
        float var = 0.f;
        #pragma unroll
        for (int e = 0; e < EE; e++) { float d = lg[e] - lmean; var += d * d; }
        var *= (1.f / EE);
        float lrstd = rsqrtf(var + 1e-5f);
        float mx = -1e30f;
        #pragma unroll
        for (int e = 0; e < EE; e++) { lg[e] = (lg[e] - lmean) * lrstd * rln_g[e] + rln_b[e]; mx = fmaxf(mx, lg[e]); }
        float den = 0.f;
        float r[EE];
        #pragma unroll
        for (int e = 0; e < EE; e++) { r[e] = __expf(lg[e] - mx); den += r[e]; }
        float inv = 1.f / den;
        const float* nrow = noise + (size_t)t * EE;
        #pragma unroll
        for (int e = 0; e < EE; e++) r[e] = r[e] * inv + nrow[e] * 0.125f;

        int i1 = 0;
        #pragma unroll
        for (int e = 1; e < EE; e++) if (r[e] > r[i1]) i1 = e;
        int i2 = (i1 == 0) ? 1 : 0;
        #pragma unroll
        for (int e = 0; e < EE; e++) if (e != i1 && r[e] > r[i2]) i2 = e;

        float vm = fmaxf(r[i1], r[i2]);
        float e1 = __expf(r[i1] - vm), e2 = __expf(r[i2] - vm);
        float wsum = 1.f / (e1 + e2);
        float w1 = e1 * wsum, w2 = e2 * wsum;

        int p1 = atomicAdd(&g_cnt[i1], 1);
        g_list[i1 * TT + p1] = t; g_wt[i1 * TT + p1] = w1;
        int p2 = atomicAdd(&g_cnt[i2], 1);
        g_list[i2 * TT + p2] = t; g_wt[i2 * TT + p2] = w2;
    }
}

__global__ void zero_cnt_kernel() { if (threadIdx.x < EE) g_cnt[threadIdx.x] = 0; }

// ---------------- fp16 GEMM, 128x128x32, 4-stage cp.async ----------------
#define BM 128
#define BN 128
#define GS 4
#define QAW 20
#define QSTG_W (BM * QAW)
#define GEMM_SMEM ((2 * GS * QSTG_W + 384) * 4)

template<int MODE>
__global__ __launch_bounds__(256, 2) void fp16_gemm_kernel(
    const __half* __restrict__ A, const __half* __restrict__ BT, float* __restrict__ Cm,
    int Nn,
    const float* __restrict__ bias, const float* __restrict__ resid,
    __nv_bfloat16* __restrict__ qb, __nv_bfloat16* __restrict__ kb,
    __nv_bfloat16* __restrict__ vtb)
{
    extern __shared__ unsigned qsm[];
    unsigned* As = qsm;
    unsigned* Bs = As + GS * QSTG_W;
    int*   stok = (int*)(Bs + GS * QSTG_W);
    float* swt  = (float*)(stok + BM);
    const int K = CC;

    int bm = blockIdx.y * BM, bn = blockIdx.x * BN;
    int tid = threadIdx.x;
    int e = 0;
    if (MODE == 1) {
        e = blockIdx.z;
        int cnt = g_cnt[e];
        if (bm >= cnt) return;
        if (tid < BM) {
            int m = bm + tid;
            if (m < cnt) { stok[tid] = g_list[e * TT + m]; swt[tid] = g_wt[e * TT + m]; }
            else         { stok[tid] = -1; swt[tid] = 0.f; }
        }
        __syncthreads();
    }

    const __half* BTb = (MODE == 1) ? (BT + (size_t)e * K * Nn) : BT;
    unsigned a_smem = (unsigned)__cvta_generic_to_shared(As);
    unsigned b_smem = (unsigned)__cvta_generic_to_shared(Bs);

    int rowF = tid >> 1;
    int segF = (tid & 1) * 2;

    auto fill_stage = [&](int s, int k0) {
        #pragma unroll
        for (int j = 0; j < 2; j++) {
            int seg = segF + j;
            const __half* srcA;
            int sz = 16;
            if (MODE == 1) {
                int tok = stok[rowF];
                if (tok >= 0) srcA = A + (size_t)tok * K + k0 + seg * 8;
                else { srcA = A; sz = 0; }
            } else {
                srcA = A + (size_t)(bm + rowF) * K + k0 + seg * 8;
            }
            cp16(a_smem + (unsigned)((s * QSTG_W + rowF * QAW + seg * 4) * 4), srcA, sz);
            const __half* srcB = BTb + (size_t)(bn + rowF) * K + k0 + seg * 8;
            cp16(b_smem + (unsigned)((s * QSTG_W + rowF * QAW + seg * 4) * 4), srcB, 16);
        }
    };

    #pragma unroll
    for (int s = 0; s < GS - 1; s++) {
        fill_stage(s, s * 32);
        asm volatile("cp.async.commit_group;" ::: "memory");
    }

    int lane = tid & 31, wid = tid >> 5;
    int wm = (wid & 3) * 32;
    int wn = (wid >> 2) * 64;
    int g = lane >> 2, c = lane & 3;

    float acc[2][8][4];
    #pragma unroll
    for (int mi = 0; mi < 2; mi++)
        #pragma unroll
        for (int ni = 0; ni < 8; ni++)
            #pragma unroll
            for (int q = 0; q < 4; q++) acc[mi][ni][q] = 0.f;

    int nIter = K / 32;
    for (int it = 0; it < nIter; it++) {
        asm volatile("cp.async.wait_group 2;" ::: "memory");
        __syncthreads();

        int nx = it + GS - 1;
        if (nx < nIter) fill_stage(nx & (GS - 1), nx * 32);
        asm volatile("cp.async.commit_group;" ::: "memory");

        const unsigned* Ab = As + (it & (GS - 1)) * QSTG_W;
        const unsigned* Bb = Bs + (it & (GS - 1)) * QSTG_W;
        #pragma unroll
        for (int kc = 0; kc < 2; kc++) {
            unsigned af[2][4];
            #pragma unroll
            for (int mi = 0; mi < 2; mi++) {
                int r0 = wm + mi * 16 + g;
                af[mi][0] = Ab[r0 * QAW + kc * 8 + c];
                af[mi][1] = Ab[(r0 + 8) * QAW + kc * 8 + c];
                af[mi][2] = Ab[r0 * QAW + kc * 8 + c + 4];
                af[mi][3] = Ab[(r0 + 8) * QAW + kc * 8 + c + 4];
            }
            #pragma unroll
            for (int ni = 0; ni < 8; ni++) {
                int nrow = wn + ni * 8 + g;
                unsigned b0 = Bb[nrow * QAW + kc * 8 + c];
                unsigned b1 = Bb[nrow * QAW + kc * 8 + c + 4];
                mma16h(acc[0][ni], af[0], b0, b1);
                mma16h(acc[1][ni], af[1], b0, b1);
            }
        }
    }

    #pragma unroll
    for (int mi = 0; mi < 2; mi++) {
        int rl0 = wm + mi * 16 + g;
        int rl1 = rl0 + 8;
        if (MODE == 1) {
            int tk0 = stok[rl0], tk1 = stok[rl1];
            float w0 = swt[rl0], w1 = swt[rl1];
            #pragma unroll
            for (int ni = 0; ni < 8; ni++) {
                int cn = bn + wn + ni * 8 + 2 * c;
                float b0 = bias[(size_t)e * Nn + cn], b1 = bias[(size_t)e * Nn + cn + 1];
                if (tk0 >= 0) {
                    float* p = Cm + (size_t)tk0 * Nn + cn;
                    atomicAdd(p,     w0 * (acc[mi][ni][0] + b0));
                    atomicAdd(p + 1, w0 * (acc[mi][ni][1] + b1));
                }
                if (tk1 >= 0) {
                    float* p = Cm + (size_t)tk1 * Nn + cn;
                    atomicAdd(p,     w1 * (acc[mi][ni][2] + b0));
                    atomicAdd(p + 1, w1 * (acc[mi][ni][3] + b1));
                }
            }
        } else if (MODE == 2) {
            int r0 = bm + rl0, r1 = bm + rl1;
            int b0r = r0 >> 10, n0 = r0 & 1023;
            int b1r = r1 >> 10, n1 = r1 & 1023;
            #pragma unroll
            for (int ni = 0; ni < 8; ni++) {
                int cn = bn + wn + ni * 8 + 2 * c;
                int sect = cn / CC;
                int cc = cn - sect * CC;
                int h = cc >> 6, d = cc & 63;
                if (sect == 0) {
                    size_t i0 = ((size_t)(b0r * HH + h) * NN + n0) * DH + d;
                    size_t i1 = ((size_t)(b1r * HH + h) * NN + n1) * DH + d;
                    *(unsigned*)&qb[i0] = f2bf2(acc[mi][ni][0] * 0.125f, acc[mi][ni][1] * 0.125f);
                    *(unsigned*)&qb[i1] = f2bf2(acc[mi][ni][2] * 0.125f, acc[mi][ni][3] * 0.125f);
                } else if (sect == 1) {
                    size_t i0 = ((size_t)(b0r * HH + h) * NN + n0) * DH + d;
                    size_t i1 = ((size_t)(b1r * HH + h) * NN + n1) * DH + d;
                    *(unsigned*)&kb[i0] = f2bf2(acc[mi][ni][0], acc[mi][ni][1]);
                    *(unsigned*)&kb[i1] = f2bf2(acc[mi][ni][2], acc[mi][ni][3]);
                } else {
                    size_t base0 = (size_t)(b0r * HH + h) * DH;
                    size_t base1 = (size_t)(b1r * HH + h) * DH;
                    vtb[(base0 + d) * NN + n0]     = __float2bfloat16_rn(acc[mi][ni][0]);
                    vtb[(base0 + d + 1) * NN + n0] = __float2bfloat16_rn(acc[mi][ni][1]);
                    vtb[(base1 + d) * NN + n1]     = __float2bfloat16_rn(acc[mi][ni][2]);
                    vtb[(base1 + d + 1) * NN + n1] = __float2bfloat16_rn(acc[mi][ni][3]);
                }
            }
        } else {
            int r0 = bm + rl0, r1 = bm + rl1;
            #pragma unroll
            for (int ni = 0; ni < 8; ni++) {
                int cn = bn + wn + ni * 8 + 2 * c;
                float2 v0 = make_float2(acc[mi][ni][0], acc[mi][ni][1]);
                float2 v1 = make_float2(acc[mi][ni][2], acc[mi][ni][3]);
                float b0 = bias[cn], b1 = bias[cn + 1];
                v0.x += b0; v0.y += b1; v1.x += b0; v1.y += b1;
                float2 r0v = *(const float2*)(resid + (size_t)r0 * Nn + cn);
                float2 r1v = *(const float2*)(resid + (size_t)r1 * Nn + cn);
                v0.x += r0v.x; v0.y += r0v.y; v1.x += r1v.x; v1.y += r1v.y;
                *(float2*)(Cm + (size_t)r0 * Nn + cn) = v0;
                *(float2*)(Cm + (size_t)r1 * Nn + cn) = v1;
            }
        }
    }
}

// ---------------- bf16 flash attention (o -> fp16) ----------------
#define QSTRW 36
#define KSTRW 36
#define ATTN_SMEM ((128*QSTRW + 2*64*KSTRW + 2*64*KSTRW) * 4)

__global__ __launch_bounds__(256, 2) void attn_bf16_kernel(
    const __nv_bfloat16* __restrict__ qb,
    const __nv_bfloat16* __restrict__ kb,
    const __nv_bfloat16* __restrict__ vt,
    __half* __restrict__ o)
{
    extern __shared__ unsigned smem_u[];
    unsigned* QPs = smem_u;
    unsigned* Ks  = QPs + 128 * QSTRW;
    unsigned* Vs  = Ks + 2 * 64 * KSTRW;

    int bh = blockIdx.y;
    int bb = bh / HH, hh = bh % HH;
    int q0 = blockIdx.x * 128;
    int tid = threadIdx.x;
    int lane = tid & 31, wid = tid >> 5;
    int wm = wid * 16;
    int g = lane >> 2, c = lane & 3;

    const __nv_bfloat16* q_head = qb + ((size_t)(bb * HH + hh) * NN + q0) * DH;
    const __nv_bfloat16* k_head = kb + (size_t)(bb * HH + hh) * NN * DH;
    const __nv_bfloat16* v_head = vt + (size_t)(bb * HH + hh) * DH * NN;

    {
        int row = tid >> 1, seg = tid & 1;
        const uint4* src = (const uint4*)(q_head + (size_t)row * DH + seg * 32);
        unsigned* dst = QPs + row * QSTRW + seg * 16;
        #pragma unroll
        for (int i = 0; i < 4; i++)
            *(uint4*)(dst + i * 4) = src[i];
    }
    __syncthreads();

    unsigned qf[4][4];
    #pragma unroll
    for (int kc = 0; kc < 4; kc++) {
        int bw = kc * 8 + c;
        qf[kc][0] = QPs[(wm + g) * QSTRW + bw];
        qf[kc][1] = QPs[(wm + g + 8) * QSTRW + bw];
        qf[kc][2] = QPs[(wm + g) * QSTRW + bw + 4];
        qf[kc][3] = QPs[(wm + g + 8) * QSTRW + bw + 4];
    }
    __syncthreads();

    float oacc[8][4];
    #pragma unroll
    for (int ni = 0; ni < 8; ni++)
        #pragma unroll
        for (int q = 0; q < 4; q++) oacc[ni][q] = 0.f;
    float m0 = -1e30f, m1 = -1e30f, l0 = 0.f, l1 = 0.f;

    int ktok = tid & 63, kseg = tid >> 6;
    int vd = tid & 63, vseg = tid >> 6;

    {
        const uint4* ksrc = (const uint4*)(k_head + (size_t)ktok * DH);
        *(uint4*)(Ks + ktok * KSTRW + kseg * 4) = ksrc[kseg];
        *(uint4*)(Ks + ktok * KSTRW + (kseg + 4) * 4) = ksrc[kseg + 4];
        const __nv_bfloat16* vrow = v_head + (size_t)vd * NN;
        *(uint4*)(Vs + vd * KSTRW + vseg * 4)       = *(const uint4*)(vrow + vseg * 8);
        *(uint4*)(Vs + vd * KSTRW + (vseg + 4) * 4) = *(const uint4*)(vrow + (vseg + 4) * 8);
    }
    __syncthreads();

    const int NTILES = NN / 64;
    for (int tile = 0; tile < NTILES; tile++) {
        int cur = tile & 1, nxt = cur ^ 1;
        const unsigned* Kb = Ks + cur * 64 * KSTRW;
        const unsigned* Vb = Vs + cur * 64 * KSTRW;
        bool more = (tile + 1 < NTILES);

        uint4 kx0, kx1, vx0, vx1;
        if (more) {
            const uint4* ksrc = (const uint4*)(k_head + (size_t)(tile + 1) * 64 * DH + (size_t)ktok * DH);
            kx0 = ksrc[kseg]; kx1 = ksrc[kseg + 4];
            const __nv_bfloat16* vrow = v_head + (size_t)vd * NN + (tile + 1) * 64;
            vx0 = *(const uint4*)(vrow + vseg * 8);
            vx1 = *(const uint4*)(vrow + (vseg + 4) * 8);
        }

        float sa[8][4];
        #pragma unroll
        for (int ni = 0; ni < 8; ni++)
            #pragma unroll
            for (int q = 0; q < 4; q++) sa[ni][q] = 0.f;
        #pragma unroll
        for (int kc = 0; kc < 4; kc++) {
            #pragma unroll
            for (int ni = 0; ni < 8; ni++) {
                int bw = (ni * 8 + g) * KSTRW + kc * 8 + c;
                mma16(sa[ni], qf[kc], Kb[bw], Kb[bw + 4]);
            }
        }

        float mx0 = -1e30f, mx1 = -1e30f;
        #pragma unroll
        for (int ni = 0; ni < 8; ni++) {
            mx0 = fmaxf(mx0, fmaxf(sa[ni][0], sa[ni][1]));
            mx1 = fmaxf(mx1, fmaxf(sa[ni][2], sa[ni][3]));
        }
        mx0 = fmaxf(mx0, __shfl_xor_sync(~0u, mx0, 1));
        mx0 = fmaxf(mx0, __shfl_xor_sync(~0u, mx0, 2));
        mx1 = fmaxf(mx1, __shfl_xor_sync(~0u, mx1, 1));
        mx1 = fmaxf(mx1, __shfl_xor_sync(~0u, mx1, 2));
        float mn0 = fmaxf(m0, mx0), mn1 = fmaxf(m1, mx1);
        float al0 = __expf(m0 - mn0), al1 = __expf(m1 - mn1);
        float sum0 = 0.f, sum1 = 0.f;
        #pragma unroll
        for (int ni = 0; ni < 8; ni++) {
            float p00 = __expf(sa[ni][0] - mn0);
            float p01 = __expf(sa[ni][1] - mn0);
            float p10 = __expf(sa[ni][2] - mn1);
            float p11 = __expf(sa[ni][3] - mn1);
            sum0 += p00 + p01; sum1 += p10 + p11;
            QPs[(wm + g) * QSTRW + ni * 4 + c]     = f2bf2(p00, p01);
            QPs[(wm + g + 8) * QSTRW + ni * 4 + c] = f2bf2(p10, p11);
        }
        sum0 += __shfl_xor_sync(~0u, sum0, 1);
        sum0 += __shfl_xor_sync(~0u, sum0, 2);
        sum1 += __shfl_xor_sync(~0u, sum1, 1);
        sum1 += __shfl_xor_sync(~0u, sum1, 2);
        l0 = l0 * al0 + sum0; l1 = l1 * al1 + sum1;
        m0 = mn0; m1 = mn1;
        #pragma unroll
        for (int ni = 0; ni < 8; ni++) {
            oacc[ni][0] *= al0; oacc[ni][1] *= al0;
            oacc[ni][2] *= al1; oacc[ni][3] *= al1;
        }
        __syncwarp();

        if (more) {
            unsigned* Kn = Ks + nxt * 64 * KSTRW;
            *(uint4*)(Kn + ktok * KSTRW + kseg * 4) = kx0;
            *(uint4*)(Kn + ktok * KSTRW + (kseg + 4) * 4) = kx1;
        }

        #pragma unroll
        for (int kc = 0; kc < 4; kc++) {
            unsigned af[4];
            int bw = kc * 8 + c;
            af[0] = QPs[(wm + g) * QSTRW + bw];
            af[1] = QPs[(wm + g + 8) * QSTRW + bw];
            af[2] = QPs[(wm + g) * QSTRW + bw + 4];
            af[3] = QPs[(wm + g + 8) * QSTRW + bw + 4];
            #pragma unroll
            for (int ni = 0; ni < 8; ni++) {
                int vw = (ni * 8 + g) * KSTRW + kc * 8 + c;
                mma16(oacc[ni], af, Vb[vw], Vb[vw + 4]);
            }
        }

        if (more) {
            unsigned* Vn = Vs + nxt * 64 * KSTRW;
            *(uint4*)(Vn + vd * KSTRW + vseg * 4) = vx0;
            *(uint4*)(Vn + vd * KSTRW + (vseg + 4) * 4) = vx1;
        }
        __syncthreads();
    }

    float inv0 = 1.f / l0, inv1 = 1.f / l1;
    size_t t0 = (size_t)bb * NN + q0 + wm + g;
    size_t t1 = t0 + 8;
    #pragma unroll
    for (int ni = 0; ni < 8; ni++) {
        int dcol = hh * DH + ni * 8 + 2 * c;
        *(__half2*)&o[t0 * CC + dcol] = __floats2half2_rn(oacc[ni][0] * inv0, oacc[ni][1] * inv0);
        *(__half2*)&o[t1 * CC + dcol] = __floats2half2_rn(oacc[ni][2] * inv1, oacc[ni][3] * inv1);
    }
}

// ---------------- launch ----------------
extern "C" void kernel_launch(void* const* d_in, const int* in_sizes, int n_in,
                              void* d_out, int out_size)
{
    const float* x       = (const float*)d_in[0];
    const float* noise   = (const float*)d_in[1];
    const float* ln1_g   = (const float*)d_in[2];
    const float* ln1_b   = (const float*)d_in[3];
    const float* qkv_w   = (const float*)d_in[4];
    const float* proj_w  = (const float*)d_in[5];
    const float* proj_b  = (const float*)d_in[6];
    const float* ln2_g   = (const float*)d_in[7];
    const float* ln2_b   = (const float*)d_in[8];
    const float* route_w = (const float*)d_in[9];
    const float* route_b = (const float*)d_in[10];
    const float* rln_g   = (const float*)d_in[11];
    const float* rln_b   = (const float*)d_in[12];
    const float* exp_w   = (const float*)d_in[13];
    const float* exp_b   = (const float*)d_in[14];
    float* out = (float*)d_out;

    __half *h1h, *oh, *h2h, *qkvwT, *projwT, *expwT;
    __nv_bfloat16 *qbp, *kbp, *vtp;
    cudaGetSymbolAddress((void**)&h1h, g_h1h);
    cudaGetSymbolAddress((void**)&oh,  g_oh);
    cudaGetSymbolAddress((void**)&h2h, g_h2h);
    cudaGetSymbolAddress((void**)&qkvwT,  g_qkvwT);
    cudaGetSymbolAddress((void**)&projwT, g_projwT);
    cudaGetSymbolAddress((void**)&expwT,  g_expwT);
    cudaGetSymbolAddress((void**)&qbp, g_qb);
    cudaGetSymbolAddress((void**)&kbp, g_kb);
    cudaGetSymbolAddress((void**)&vtp, g_vt);

    cudaFuncSetAttribute(attn_bf16_kernel, cudaFuncAttributeMaxDynamicSharedMemorySize, (int)ATTN_SMEM);
    cudaFuncSetAttribute(fp16_gemm_kernel<0>, cudaFuncAttributeMaxDynamicSharedMemorySize, (int)GEMM_SMEM);
    cudaFuncSetAttribute(fp16_gemm_kernel<1>, cudaFuncAttributeMaxDynamicSharedMemorySize, (int)GEMM_SMEM);
    cudaFuncSetAttribute(fp16_gemm_kernel<2>, cudaFuncAttributeMaxDynamicSharedMemorySize, (int)GEMM_SMEM);

    // 0) weight transpose -> fp16 [n][k]
    transpose_half_kernel<<<dim3(3 * CC / 32, CC / 32), 256>>>(qkv_w, qkvwT, CC, 3 * CC);
    transpose_half_kernel<<<dim3(CC / 32, CC / 32), 256>>>(proj_w, projwT, CC, CC);
    transpose_half_kernel<<<dim3(CC / 32, CC / 32, EE), 256>>>(exp_w, expwT, CC, CC);
    // 1) LN1 -> fp16 h1
    ln1_kernel<<<TT, 192>>>(x, ln1_g, ln1_b, h1h);
    // 2) QKV GEMM (fp16 mma) -> bf16 q/k/vt
    fp16_gemm_kernel<2><<<dim3(3 * CC / BN, TT / BM), 256, GEMM_SMEM>>>(
        h1h, qkvwT, nullptr, 3 * CC, nullptr, nullptr, qbp, kbp, vtp);
    // 3) attention -> fp16 o
    attn_bf16_kernel<<<dim3(NN / 128, BB * HH), 256, ATTN_SMEM>>>(qbp, kbp, vtp, oh);
    // 4) proj + bias + residual -> d_out
    fp16_gemm_kernel<0><<<dim3(CC / BN, TT / BM), 256, GEMM_SMEM>>>(
        oh, projwT, out, CC, proj_b, x, nullptr, nullptr, nullptr);
    // 5) fused LN2 + router -> fp16 h2h + expert lists
    zero_cnt_kernel<<<1, 32>>>();
    ln2_route_kernel<<<TT, 192>>>(out, ln2_g, ln2_b, h2h,
                                  route_w, route_b, rln_g, rln_b, noise);
    // 6) MoE grouped GEMM (fp16 mma), atomicAdd into d_out
    fp16_gemm_kernel<1><<<dim3(CC / BN, TT / BM, EE), 256, GEMM_SMEM>>>(
        h2h, expwT, out, CC, exp_b, nullptr, nullptr, nullptr, nullptr);
}

// round 15
// speedup vs baseline: 1.4274x; 1.0151x over previous
#include <cuda_runtime.h>
#include <cuda_bf16.h>
#include <cuda_fp16.h>
#include <math.h>
#include <stdint.h>

#define BB 16
#define NN 1024
#define CC 768
#define HH 12
#define DH 64
#define EE 8
#define TT (BB*NN)

// ---------------- scratch (no allocations allowed) ----------------
__device__ __half g_h1h[(size_t)TT * CC];            // LN1 output (fp16)
__device__ __nv_bfloat16 g_qb[(size_t)TT * CC];      // Q  [b][h][n][d]  (pre-scaled)
__device__ __nv_bfloat16 g_kb[(size_t)TT * CC];      // K  [b][h][n][d]
__device__ __nv_bfloat16 g_vb[(size_t)TT * CC];      // V  [b][h][n][d]  (token-major now)
__device__ __half g_oh[(size_t)TT * CC];             // attention output (fp16)
__device__ __half g_h2h[(size_t)TT * CC];            // LN2 output (fp16, MoE A)
__device__ __half g_qkvwT[(size_t)3 * CC * CC];      // fp16 transposed weights [n][k]
__device__ __half g_projwT[(size_t)CC * CC];
__device__ __half g_expwT[(size_t)EE * CC * CC];
__device__ int   g_cnt[EE];
__device__ int   g_list[EE * TT];
__device__ float g_wt[EE * TT];

// ---------------- helpers ----------------
__device__ __forceinline__ unsigned f2bf2(float lo, float hi) {
    __nv_bfloat162 h = __floats2bfloat162_rn(lo, hi);
    return *reinterpret_cast<unsigned*>(&h);
}
__device__ __forceinline__ void mma16(float* c, const unsigned* a, unsigned b0, unsigned b1) {
    asm volatile("mma.sync.aligned.m16n8k16.row.col.f32.bf16.bf16.f32 "
        "{%0,%1,%2,%3}, {%4,%5,%6,%7}, {%8,%9}, {%0,%1,%2,%3};"
        : "+f"(c[0]), "+f"(c[1]), "+f"(c[2]), "+f"(c[3])
        : "r"(a[0]), "r"(a[1]), "r"(a[2]), "r"(a[3]), "r"(b0), "r"(b1));
}
__device__ __forceinline__ void mma16h(float* c, const unsigned* a, unsigned b0, unsigned b1) {
    asm volatile("mma.sync.aligned.m16n8k16.row.col.f32.f16.f16.f32 "
        "{%0,%1,%2,%3}, {%4,%5,%6,%7}, {%8,%9}, {%0,%1,%2,%3};"
        : "+f"(c[0]), "+f"(c[1]), "+f"(c[2]), "+f"(c[3])
        : "r"(a[0]), "r"(a[1]), "r"(a[2]), "r"(a[3]), "r"(b0), "r"(b1));
}
__device__ __forceinline__ void cp16(unsigned dst, const void* src, int sz) {
    asm volatile("cp.async.cg.shared.global [%0], [%1], 16, %2;"
        :: "r"(dst), "l"(src), "r"(sz) : "memory");
}

// ---------------- weight transposes -> fp16 [n][k] ----------------
__global__ __launch_bounds__(256) void transpose_half_kernel(
    const float* __restrict__ in, __half* __restrict__ out, int R, int Cc)
{
    __shared__ float t[32][33];
    int bx = blockIdx.x * 32, by = blockIdx.y * 32;
    int tx = threadIdx.x & 31, ty = threadIdx.x >> 5;
    #pragma unroll
    for (int j = 0; j < 4; j++)
        t[ty + j * 8][tx] = in[(size_t)(by + ty + j * 8) * Cc + bx + tx];
    __syncthreads();
    #pragma unroll
    for (int j = 0; j < 4; j++)
        out[(size_t)(bx + ty + j * 8) * R + by + tx] = __float2half_rn(t[tx][ty + j * 8]);
}

// z in [0,8): expert z ; z==8: proj
__global__ __launch_bounds__(256) void transpose_ep_kernel(
    const float* __restrict__ exp_w, __half* __restrict__ expT,
    const float* __restrict__ proj_w, __half* __restrict__ projT)
{
    __shared__ float t[32][33];
    int z = blockIdx.z;
    const float* in = (z < EE) ? exp_w + (size_t)z * CC * CC : proj_w;
    __half* out = (z < EE) ? expT + (size_t)z * CC * CC : projT;
    int bx = blockIdx.x * 32, by = blockIdx.y * 32;
    int tx = threadIdx.x & 31, ty = threadIdx.x >> 5;
    #pragma unroll
    for (int j = 0; j < 4; j++)
        t[ty + j * 8][tx] = in[(size_t)(by + ty + j * 8) * CC + bx + tx];
    __syncthreads();
    #pragma unroll
    for (int j = 0; j < 4; j++)
        out[(size_t)(bx + ty + j * 8) * CC + by + tx] = __float2half_rn(t[tx][ty + j * 8]);
}

// ---------------- LN1 (zeroes g_cnt in block 0) ----------------
__global__ __launch_bounds__(192) void ln1_kernel(const float* __restrict__ in,
    const float* __restrict__ gamma, const float* __restrict__ beta,
    __half* __restrict__ outh)
{
    if (blockIdx.x == 0 && threadIdx.x < EE) g_cnt[threadIdx.x] = 0;
    int t = blockIdx.x;
    int c = threadIdx.x * 4;
    const float* row = in + (size_t)t * CC;
    float4 v4 = *(const float4*)(row + c);
    float s = v4.x + v4.y + v4.z + v4.w;
    float s2 = v4.x * v4.x + v4.y * v4.y + v4.z * v4.z + v4.w * v4.w;
    __shared__ float sh[16];
    #pragma unroll
    for (int o = 16; o > 0; o >>= 1) { s += __shfl_xor_sync(~0u, s, o); s2 += __shfl_xor_sync(~0u, s2, o); }
    int w = threadIdx.x >> 5, l = threadIdx.x & 31;
    if (l == 0) { sh[w] = s; sh[8 + w] = s2; }
    __syncthreads();
    if (threadIdx.x == 0) {
        float a = 0.f, b = 0.f;
        #pragma unroll
        for (int i = 0; i < 6; i++) { a += sh[i]; b += sh[8 + i]; }
        sh[0] = a; sh[1] = b;
    }
    __syncthreads();
    float mean = sh[0] * (1.f / CC);
    float rstd = rsqrtf(sh[1] * (1.f / CC) - mean * mean + 1e-5f);
    float4 gv = *(const float4*)(gamma + c);
    float4 bv = *(const float4*)(beta + c);
    __half2* op = (__half2*)(outh + (size_t)t * CC + c);
    op[0] = __floats2half2_rn((v4.x - mean) * rstd * gv.x + bv.x, (v4.y - mean) * rstd * gv.y + bv.y);
    op[1] = __floats2half2_rn((v4.z - mean) * rstd * gv.z + bv.z, (v4.w - mean) * rstd * gv.w + bv.w);
}

// ---------------- fused LN2 + router ----------------
__global__ __launch_bounds__(192) void ln2_route_kernel(const float* __restrict__ in,
    const float* __restrict__ gamma, const float* __restrict__ beta,
    __half* __restrict__ outh,
    const float* __restrict__ route_w, const float* __restrict__ route_b,
    const float* __restrict__ rln_g, const float* __restrict__ rln_b,
    const float* __restrict__ noise)
{
    int t = blockIdx.x;
    int c = threadIdx.x * 4;
    const float* row = in + (size_t)t * CC;
    float4 v4 = *(const float4*)(row + c);
    float s = v4.x + v4.y + v4.z + v4.w;
    float s2 = v4.x * v4.x + v4.y * v4.y + v4.z * v4.z + v4.w * v4.w;
    __shared__ float sh[16];
    __shared__ float shacc[6][EE];
    #pragma unroll
    for (int o = 16; o > 0; o >>= 1) { s += __shfl_xor_sync(~0u, s, o); s2 += __shfl_xor_sync(~0u, s2, o); }
    int w = threadIdx.x >> 5, l = threadIdx.x & 31;
    if (l == 0) { sh[w] = s; sh[8 + w] = s2; }
    __syncthreads();
    if (threadIdx.x == 0) {
        float a = 0.f, b = 0.f;
        #pragma unroll
        for (int i = 0; i < 6; i++) { a += sh[i]; b += sh[8 + i]; }
        sh[0] = a; sh[1] = b;
    }
    __syncthreads();
    float mean = sh[0] * (1.f / CC);
    float rstd = rsqrtf(sh[1] * (1.f / CC) - mean * mean + 1e-5f);
    float4 gv = *(const float4*)(gamma + c);
    float4 bv = *(const float4*)(beta + c);
    float v[4];
    v[0] = (v4.x - mean) * rstd * gv.x + bv.x;
    v[1] = (v4.y - mean) * rstd * gv.y + bv.y;
    v[2] = (v4.z - mean) * rstd * gv.z + bv.z;
    v[3] = (v4.w - mean) * rstd * gv.w + bv.w;
    __half2* op = (__half2*)(outh + (size_t)t * CC + c);
    op[0] = __floats2half2_rn(v[0], v[1]);
    op[1] = __floats2half2_rn(v[2], v[3]);

    float acc[EE];
    #pragma unroll
    for (int e = 0; e < EE; e++) acc[e] = 0.f;
    #pragma unroll
    for (int i = 0; i < 4; i++) {
        const float4* rw = (const float4*)(route_w + (size_t)(c + i) * EE);
        float4 r0 = rw[0], r1 = rw[1];
        acc[0] += v[i] * r0.x; acc[1] += v[i] * r0.y;
        acc[2] += v[i] * r0.z; acc[3] += v[i] * r0.w;
        acc[4] += v[i] * r1.x; acc[5] += v[i] * r1.y;
        acc[6] += v[i] * r1.z; acc[7] += v[i] * r1.w;
    }
    #pragma unroll
    for (int e = 0; e < EE; e++)
        #pragma unroll
        for (int o = 16; o > 0; o >>= 1)
            acc[e] += __shfl_xor_sync(~0u, acc[e], o);
    if (l == 0) {
        #pragma unroll
        for (int e = 0; e < EE; e++) shacc[w][e] = acc[e];
    }
    __syncthreads();
    if (threadIdx.x == 0) {
        float lg[EE];
        float lmean = 0.f;
        #pragma unroll
        for (int e = 0; e < EE; e++) {
            float a = 0.f;
            #pragma unroll
            for (int i = 0; i < 6; i++) a += shacc[i][e];
            lg[e] = a + route_b[e];
            lmean += lg[e];
        }
        lmean *= (1.f / EE);
        float var = 0.f;
        #pragma unroll
        for (int e = 0; e < EE; e++) { float d = lg[e] - lmean; var += d * d; }
        var *= (1.f / EE);
        float lrstd = rsqrtf(var + 1e-5f);
        float mx = -1e30f;
        #pragma unroll
        for (int e = 0; e < EE; e++) { lg[e] = (lg[e] - lmean) * lrstd * rln_g[e] + rln_b[e]; mx = fmaxf(mx, lg[e]); }
        float den = 0.f;
        float r[EE];
        #pragma unroll
        for (int e = 0; e < EE; e++) { r[e] = __expf(lg[e] - mx); den += r[e]; }
        float inv = 1.f / den;
        const float* nrow = noise + (size_t)t * EE;
        #pragma unroll
        for (int e = 0; e < EE; e++) r[e] = r[e] * inv + nrow[e] * 0.125f;

        int i1 = 0;
        #pragma unroll
        for (int e = 1; e < EE; e++) if (r[e] > r[i1]) i1 = e;
        int i2 = (i1 == 0) ? 1 : 0;
        #pragma unroll
        for (int e = 0; e < EE; e++) if (e != i1 && r[e] > r[i2]) i2 = e;

        float vm = fmaxf(r[i1], r[i2]);
        float e1 = __expf(r[i1] - vm), e2 = __expf(r[i2] - vm);
        float wsum = 1.f / (e1 + e2);
        float w1 = e1 * wsum, w2 = e2 * wsum;

        int p1 = atomicAdd(&g_cnt[i1], 1);
        g_list[i1 * TT + p1] = t; g_wt[i1 * TT + p1] = w1;
        int p2 = atomicAdd(&g_cnt[i2], 1);
        g_list[i2 * TT + p2] = t; g_wt[i2 * TT + p2] = w2;
    }
}

// ---------------- fp16 GEMM, 128x128x32, 4-stage cp.async ----------------
#define BM 128
#define BN 128
#define GS 4
#define QAW 20
#define QSTG_W (BM * QAW)
#define GEMM_SMEM ((2 * GS * QSTG_W + 384) * 4)

template<int MODE>
__global__ __launch_bounds__(256, 2) void fp16_gemm_kernel(
    const __half* __restrict__ A, const __half* __restrict__ BT, float* __restrict__ Cm,
    int Nn,
    const float* __restrict__ bias, const float* __restrict__ resid,
    __nv_bfloat16* __restrict__ qb, __nv_bfloat16* __restrict__ kb,
    __nv_bfloat16* __restrict__ vb)
{
    extern __shared__ unsigned qsm[];
    unsigned* As = qsm;
    unsigned* Bs = As + GS * QSTG_W;
    int*   stok = (int*)(Bs + GS * QSTG_W);
    float* swt  = (float*)(stok + BM);
    const int K = CC;

    int bm = blockIdx.y * BM, bn = blockIdx.x * BN;
    int tid = threadIdx.x;
    int e = 0;
    if (MODE == 1) {
        e = blockIdx.z;
        int cnt = g_cnt[e];
        if (bm >= cnt) return;
        if (tid < BM) {
            int m = bm + tid;
            if (m < cnt) { stok[tid] = g_list[e * TT + m]; swt[tid] = g_wt[e * TT + m]; }
            else         { stok[tid] = -1; swt[tid] = 0.f; }
        }
        __syncthreads();
    }

    const __half* BTb = (MODE == 1) ? (BT + (size_t)e * K * Nn) : BT;
    unsigned a_smem = (unsigned)__cvta_generic_to_shared(As);
    unsigned b_smem = (unsigned)__cvta_generic_to_shared(Bs);

    int rowF = tid >> 1;
    int segF = (tid & 1) * 2;

    auto fill_stage = [&](int s, int k0) {
        #pragma unroll
        for (int j = 0; j < 2; j++) {
            int seg = segF + j;
            const __half* srcA;
            int sz = 16;
            if (MODE == 1) {
                int tok = stok[rowF];
                if (tok >= 0) srcA = A + (size_t)tok * K + k0 + seg * 8;
                else { srcA = A; sz = 0; }
            } else {
                srcA = A + (size_t)(bm + rowF) * K + k0 + seg * 8;
            }
            cp16(a_smem + (unsigned)((s * QSTG_W + rowF * QAW + seg * 4) * 4), srcA, sz);
            const __half* srcB = BTb + (size_t)(bn + rowF) * K + k0 + seg * 8;
            cp16(b_smem + (unsigned)((s * QSTG_W + rowF * QAW + seg * 4) * 4), srcB, 16);
        }
    };

    #pragma unroll
    for (int s = 0; s < GS - 1; s++) {
        fill_stage(s, s * 32);
        asm volatile("cp.async.commit_group;" ::: "memory");
    }

    int lane = tid & 31, wid = tid >> 5;
    int wm = (wid & 3) * 32;
    int wn = (wid >> 2) * 64;
    int g = lane >> 2, c = lane & 3;

    float acc[2][8][4];
    #pragma unroll
    for (int mi = 0; mi < 2; mi++)
        #pragma unroll
        for (int ni = 0; ni < 8; ni++)
            #pragma unroll
            for (int q = 0; q < 4; q++) acc[mi][ni][q] = 0.f;

    int nIter = K / 32;
    for (int it = 0; it < nIter; it++) {
        asm volatile("cp.async.wait_group 2;" ::: "memory");
        __syncthreads();

        int nx = it + GS - 1;
        if (nx < nIter) fill_stage(nx & (GS - 1), nx * 32);
        asm volatile("cp.async.commit_group;" ::: "memory");

        const unsigned* Ab = As + (it & (GS - 1)) * QSTG_W;
        const unsigned* Bb = Bs + (it & (GS - 1)) * QSTG_W;
        #pragma unroll
        for (int kc = 0; kc < 2; kc++) {
            unsigned af[2][4];
            #pragma unroll
            for (int mi = 0; mi < 2; mi++) {
                int r0 = wm + mi * 16 + g;
                af[mi][0] = Ab[r0 * QAW + kc * 8 + c];
                af[mi][1] = Ab[(r0 + 8) * QAW + kc * 8 + c];
                af[mi][2] = Ab[r0 * QAW + kc * 8 + c + 4];
                af[mi][3] = Ab[(r0 + 8) * QAW + kc * 8 + c + 4];
            }
            #pragma unroll
            for (int ni = 0; ni < 8; ni++) {
                int nrow = wn + ni * 8 + g;
                unsigned b0 = Bb[nrow * QAW + kc * 8 + c];
                unsigned b1 = Bb[nrow * QAW + kc * 8 + c + 4];
                mma16h(acc[0][ni], af[0], b0, b1);
                mma16h(acc[1][ni], af[1], b0, b1);
            }
        }
    }

    #pragma unroll
    for (int mi = 0; mi < 2; mi++) {
        int rl0 = wm + mi * 16 + g;
        int rl1 = rl0 + 8;
        if (MODE == 1) {
            int tk0 = stok[rl0], tk1 = stok[rl1];
            float w0 = swt[rl0], w1 = swt[rl1];
            #pragma unroll
            for (int ni = 0; ni < 8; ni++) {
                int cn = bn + wn + ni * 8 + 2 * c;
                float b0 = bias[(size_t)e * Nn + cn], b1 = bias[(size_t)e * Nn + cn + 1];
                if (tk0 >= 0) {
                    float* p = Cm + (size_t)tk0 * Nn + cn;
                    atomicAdd(p,     w0 * (acc[mi][ni][0] + b0));
                    atomicAdd(p + 1, w0 * (acc[mi][ni][1] + b1));
                }
                if (tk1 >= 0) {
                    float* p = Cm + (size_t)tk1 * Nn + cn;
                    atomicAdd(p,     w1 * (acc[mi][ni][2] + b0));
                    atomicAdd(p + 1, w1 * (acc[mi][ni][3] + b1));
                }
            }
        } else if (MODE == 2) {
            int r0 = bm + rl0, r1 = bm + rl1;
            int b0r = r0 >> 10, n0 = r0 & 1023;
            int b1r = r1 >> 10, n1 = r1 & 1023;
            #pragma unroll
            for (int ni = 0; ni < 8; ni++) {
                int cn = bn + wn + ni * 8 + 2 * c;
                int sect = cn / CC;
                int cc = cn - sect * CC;
                int h = cc >> 6, d = cc & 63;
                size_t i0 = ((size_t)(b0r * HH + h) * NN + n0) * DH + d;
                size_t i1 = ((size_t)(b1r * HH + h) * NN + n1) * DH + d;
                if (sect == 0) {
                    *(unsigned*)&qb[i0] = f2bf2(acc[mi][ni][0] * 0.125f, acc[mi][ni][1] * 0.125f);
                    *(unsigned*)&qb[i1] = f2bf2(acc[mi][ni][2] * 0.125f, acc[mi][ni][3] * 0.125f);
                } else if (sect == 1) {
                    *(unsigned*)&kb[i0] = f2bf2(acc[mi][ni][0], acc[mi][ni][1]);
                    *(unsigned*)&kb[i1] = f2bf2(acc[mi][ni][2], acc[mi][ni][3]);
                } else {
                    *(unsigned*)&vb[i0] = f2bf2(acc[mi][ni][0], acc[mi][ni][1]);
                    *(unsigned*)&vb[i1] = f2bf2(acc[mi][ni][2], acc[mi][ni][3]);
                }
            }
        } else {
            int r0 = bm + rl0, r1 = bm + rl1;
            #pragma unroll
            for (int ni = 0; ni < 8; ni++) {
                int cn = bn + wn + ni * 8 + 2 * c;
                float2 v0 = make_float2(acc[mi][ni][0], acc[mi][ni][1]);
                float2 v1 = make_float2(acc[mi][ni][2], acc[mi][ni][3]);
                float b0 = bias[cn], b1 = bias[cn + 1];
                v0.x += b0; v0.y += b1; v1.x += b0; v1.y += b1;
                float2 r0v = *(const float2*)(resid + (size_t)r0 * Nn + cn);
                float2 r1v = *(const float2*)(resid + (size_t)r1 * Nn + cn);
                v0.x += r0v.x; v0.y += r0v.y; v1.x += r1v.x; v1.y += r1v.y;
                *(float2*)(Cm + (size_t)r0 * Nn + cn) = v0;
                *(float2*)(Cm + (size_t)r1 * Nn + cn) = v1;
            }
        }
    }
}

// ---------------- bf16 flash attention (V transposed in smem fill) ----------------
#define QSTRW 36
#define KSTRW 36
#define ATTN_SMEM ((128*QSTRW + 2*64*KSTRW + 2*64*KSTRW) * 4)

__global__ __launch_bounds__(256, 2) void attn_bf16_kernel(
    const __nv_bfloat16* __restrict__ qb,
    const __nv_bfloat16* __restrict__ kb,
    const __nv_bfloat16* __restrict__ vb,
    __half* __restrict__ o)
{
    extern __shared__ unsigned smem_u[];
    unsigned* QPs = smem_u;
    unsigned* Ks  = QPs + 128 * QSTRW;
    unsigned* Vs  = Ks + 2 * 64 * KSTRW;

    int bh = blockIdx.y;
    int bb = bh / HH, hh = bh % HH;
    int q0 = blockIdx.x * 128;
    int tid = threadIdx.x;
    int lane = tid & 31, wid = tid >> 5;
    int wm = wid * 16;
    int g = lane >> 2, c = lane & 3;

    const __nv_bfloat16* q_head = qb + ((size_t)(bb * HH + hh) * NN + q0) * DH;
    const __nv_bfloat16* k_head = kb + (size_t)(bb * HH + hh) * NN * DH;
    const __nv_bfloat16* v_head = vb + (size_t)(bb * HH + hh) * NN * DH;

    {
        int row = tid >> 1, seg = tid & 1;
        const uint4* src = (const uint4*)(q_head + (size_t)row * DH + seg * 32);
        unsigned* dst = QPs + row * QSTRW + seg * 16;
        #pragma unroll
        for (int i = 0; i < 4; i++)
            *(uint4*)(dst + i * 4) = src[i];
    }
    __syncthreads();

    unsigned qf[4][4];
    #pragma unroll
    for (int kc = 0; kc < 4; kc++) {
        int bw = kc * 8 + c;
        qf[kc][0] = QPs[(wm + g) * QSTRW + bw];
        qf[kc][1] = QPs[(wm + g + 8) * QSTRW + bw];
        qf[kc][2] = QPs[(wm + g) * QSTRW + bw + 4];
        qf[kc][3] = QPs[(wm + g + 8) * QSTRW + bw + 4];
    }
    __syncthreads();

    float oacc[8][4];
    #pragma unroll
    for (int ni = 0; ni < 8; ni++)
        #pragma unroll
        for (int q = 0; q < 4; q++) oacc[ni][q] = 0.f;
    float m0 = -1e30f, m1 = -1e30f, l0 = 0.f, l1 = 0.f;

    int ktok = tid & 63, kseg = tid >> 6;   // same coords for V

    // helper: store a uint4 (8 bf16 of row vtok, d seg*8..+7) transposed into Vs
    __nv_bfloat16* Vh0 = (__nv_bfloat16*)Vs;
    auto store_v = [&](__nv_bfloat16* Vh, int seg, uint4 u) {
        const __nv_bfloat16* p = (const __nv_bfloat16*)&u;
        #pragma unroll
        for (int i = 0; i < 8; i++)
            Vh[(seg * 8 + i) * 72 + ktok] = p[i];
    };

    {
        const uint4* ksrc = (const uint4*)(k_head + (size_t)ktok * DH);
        *(uint4*)(Ks + ktok * KSTRW + kseg * 4) = ksrc[kseg];
        *(uint4*)(Ks + ktok * KSTRW + (kseg + 4) * 4) = ksrc[kseg + 4];
        const uint4* vsrc = (const uint4*)(v_head + (size_t)ktok * DH);
        store_v(Vh0, kseg, vsrc[kseg]);
        store_v(Vh0, kseg + 4, vsrc[kseg + 4]);
    }
    __syncthreads();

    const int NTILES = NN / 64;
    for (int tile = 0; tile < NTILES; tile++) {
        int cur = tile & 1, nxt = cur ^ 1;
        const unsigned* Kb = Ks + cur * 64 * KSTRW;
        const unsigned* Vb = Vs + cur * 64 * KSTRW;
        bool more = (tile + 1 < NTILES);

        uint4 kx0, kx1, vx0, vx1;
        if (more) {
            const uint4* ksrc = (const uint4*)(k_head + (size_t)(tile + 1) * 64 * DH + (size_t)ktok * DH);
            kx0 = ksrc[kseg]; kx1 = ksrc[kseg + 4];
            const uint4* vsrc = (const uint4*)(v_head + (size_t)(tile + 1) * 64 * DH + (size_t)ktok * DH);
            vx0 = vsrc[kseg]; vx1 = vsrc[kseg + 4];
        }

        float sa[8][4];
        #pragma unroll
        for (int ni = 0; ni < 8; ni++)
            #pragma unroll
            for (int q = 0; q < 4; q++) sa[ni][q] = 0.f;
        #pragma unroll
        for (int kc = 0; kc < 4; kc++) {
            #pragma unroll
            for (int ni = 0; ni < 8; ni++) {
                int bw = (ni * 8 + g) * KSTRW + kc * 8 + c;
                mma16(sa[ni], qf[kc], Kb[bw], Kb[bw + 4]);
            }
        }

        float mx0 = -1e30f, mx1 = -1e30f;
        #pragma unroll
        for (int ni = 0; ni < 8; ni++) {
            mx0 = fmaxf(mx0, fmaxf(sa[ni][0], sa[ni][1]));
            mx1 = fmaxf(mx1, fmaxf(sa[ni][2], sa[ni][3]));
        }
        mx0 = fmaxf(mx0, __shfl_xor_sync(~0u, mx0, 1));
        mx0 = fmaxf(mx0, __shfl_xor_sync(~0u, mx0, 2));
        mx1 = fmaxf(mx1, __shfl_xor_sync(~0u, mx1, 1));
        mx1 = fmaxf(mx1, __shfl_xor_sync(~0u, mx1, 2));
        float mn0 = fmaxf(m0, mx0), mn1 = fmaxf(m1, mx1);
        float al0 = __expf(m0 - mn0), al1 = __expf(m1 - mn1);
        float sum0 = 0.f, sum1 = 0.f;
        #pragma unroll
        for (int ni = 0; ni < 8; ni++) {
            float p00 = __expf(sa[ni][0] - mn0);
            float p01 = __expf(sa[ni][1] - mn0);
            float p10 = __expf(sa[ni][2] - mn1);
            float p11 = __expf(sa[ni][3] - mn1);
            sum0 += p00 + p01; sum1 += p10 + p11;
            QPs[(wm + g) * QSTRW + ni * 4 + c]     = f2bf2(p00, p01);
            QPs[(wm + g + 8) * QSTRW + ni * 4 + c] = f2bf2(p10, p11);
        }
        sum0 += __shfl_xor_sync(~0u, sum0, 1);
        sum0 += __shfl_xor_sync(~0u, sum0, 2);
        sum1 += __shfl_xor_sync(~0u, sum1, 1);
        sum1 += __shfl_xor_sync(~0u, sum1, 2);
        l0 = l0 * al0 + sum0; l1 = l1 * al1 + sum1;
        m0 = mn0; m1 = mn1;
        #pragma unroll
        for (int ni = 0; ni < 8; ni++) {
            oacc[ni][0] *= al0; oacc[ni][1] *= al0;
            oacc[ni][2] *= al1; oacc[ni][3] *= al1;
        }
        __syncwarp();

        if (more) {
            unsigned* Kn = Ks + nxt * 64 * KSTRW;
            *(uint4*)(Kn + ktok * KSTRW + kseg * 4) = kx0;
            *(uint4*)(Kn + ktok * KSTRW + (kseg + 4) * 4) = kx1;
        }

        #pragma unroll
        for (int kc = 0; kc < 4; kc++) {
            unsigned af[4];
            int bw = kc * 8 + c;
            af[0] = QPs[(wm + g) * QSTRW + bw];
            af[1] = QPs[(wm + g + 8) * QSTRW + bw];
            af[2] = QPs[(wm + g) * QSTRW + bw + 4];
            af[3] = QPs[(wm + g + 8) * QSTRW + bw + 4];
            #pragma unroll
            for (int ni = 0; ni < 8; ni++) {
                int vw = (ni * 8 + g) * KSTRW + kc * 8 + c;
                mma16(oacc[ni], af, Vb[vw], Vb[vw + 4]);
            }
        }

        if (more) {
            __nv_bfloat16* Vn = (__nv_bfloat16*)(Vs + nxt * 64 * KSTRW);
            store_v(Vn, kseg, vx0);
            store_v(Vn, kseg + 4, vx1);
        }
        __syncthreads();
    }

    float inv0 = 1.f / l0, inv1 = 1.f / l1;
    size_t t0 = (size_t)bb * NN + q0 + wm + g;
    size_t t1 = t0 + 8;
    #pragma unroll
    for (int ni = 0; ni < 8; ni++) {
        int dcol = hh * DH + ni * 8 + 2 * c;
        *(__half2*)&o[t0 * CC + dcol] = __floats2half2_rn(oacc[ni][0] * inv0, oacc[ni][1] * inv0);
        *(__half2*)&o[t1 * CC + dcol] = __floats2half2_rn(oacc[ni][2] * inv1, oacc[ni][3] * inv1);
    }
}

// ---------------- launch ----------------
extern "C" void kernel_launch(void* const* d_in, const int* in_sizes, int n_in,
                              void* d_out, int out_size)
{
    const float* x       = (const float*)d_in[0];
    const float* noise   = (const float*)d_in[1];
    const float* ln1_g   = (const float*)d_in[2];
    const float* ln1_b   = (const float*)d_in[3];
    const float* qkv_w   = (const float*)d_in[4];
    const float* proj_w  = (const float*)d_in[5];
    const float* proj_b  = (const float*)d_in[6];
    const float* ln2_g   = (const float*)d_in[7];
    const float* ln2_b   = (const float*)d_in[8];
    const float* route_w = (const float*)d_in[9];
    const float* route_b = (const float*)d_in[10];
    const float* rln_g   = (const float*)d_in[11];
    const float* rln_b   = (const float*)d_in[12];
    const float* exp_w   = (const float*)d_in[13];
    const float* exp_b   = (const float*)d_in[14];
    float* out = (float*)d_out;

    __half *h1h, *oh, *h2h, *qkvwT, *projwT, *expwT;
    __nv_bfloat16 *qbp, *kbp, *vbp;
    cudaGetSymbolAddress((void**)&h1h, g_h1h);
    cudaGetSymbolAddress((void**)&oh,  g_oh);
    cudaGetSymbolAddress((void**)&h2h, g_h2h);
    cudaGetSymbolAddress((void**)&qkvwT,  g_qkvwT);
    cudaGetSymbolAddress((void**)&projwT, g_projwT);
    cudaGetSymbolAddress((void**)&expwT,  g_expwT);
    cudaGetSymbolAddress((void**)&qbp, g_qb);
    cudaGetSymbolAddress((void**)&kbp, g_kb);
    cudaGetSymbolAddress((void**)&vbp, g_vb);

    cudaFuncSetAttribute(attn_bf16_kernel, cudaFuncAttributeMaxDynamicSharedMemorySize, (int)ATTN_SMEM);
    cudaFuncSetAttribute(fp16_gemm_kernel<0>, cudaFuncAttributeMaxDynamicSharedMemorySize, (int)GEMM_SMEM);
    cudaFuncSetAttribute(fp16_gemm_kernel<1>, cudaFuncAttributeMaxDynamicSharedMemorySize, (int)GEMM_SMEM);
    cudaFuncSetAttribute(fp16_gemm_kernel<2>, cudaFuncAttributeMaxDynamicSharedMemorySize, (int)GEMM_SMEM);

    // 0) weight transposes -> fp16 [n][k]
    transpose_half_kernel<<<dim3(3 * CC / 32, CC / 32), 256>>>(qkv_w, qkvwT, CC, 3 * CC);
    transpose_ep_kernel<<<dim3(CC / 32, CC / 32, EE + 1), 256>>>(exp_w, expwT, proj_w, projwT);
    // 1) LN1 -> fp16 h1 (+ zero g_cnt)
    ln1_kernel<<<TT, 192>>>(x, ln1_g, ln1_b, h1h);
    // 2) QKV GEMM (fp16 mma) -> bf16 q/k/v (all token-major)
    fp16_gemm_kernel<2><<<dim3(3 * CC / BN, TT / BM), 256, GEMM_SMEM>>>(
        h1h, qkvwT, nullptr, 3 * CC, nullptr, nullptr, qbp, kbp, vbp);
    // 3) attention -> fp16 o
    attn_bf16_kernel<<<dim3(NN / 128, BB * HH), 256, ATTN_SMEM>>>(qbp, kbp, vbp, oh);
    // 4) proj + bias + residual -> d_out
    fp16_gemm_kernel<0><<<dim3(CC / BN, TT / BM), 256, GEMM_SMEM>>>(
        oh, projwT, out, CC, proj_b, x, nullptr, nullptr, nullptr);
    // 5) fused LN2 + router -> fp16 h2h + expert lists
    ln2_route_kernel<<<TT, 192>>>(out, ln2_g, ln2_b, h2h,
                                  route_w, route_b, rln_g, rln_b, noise);
    // 6) MoE grouped GEMM (fp16 mma), atomicAdd into d_out
    fp16_gemm_kernel<1><<<dim3(CC / BN, TT / BM, EE), 256, GEMM_SMEM>>>(
        h2h, expwT, out, CC, exp_b, nullptr, nullptr, nullptr, nullptr);
}

// round 16
// speedup vs baseline: 1.5362x; 1.0762x over previous
#include <cuda_runtime.h>
#include <cuda_bf16.h>
#include <cuda_fp16.h>
#include <math.h>
#include <stdint.h>

#define BB 16
#define NN 1024
#define CC 768
#define HH 12
#define DH 64
#define EE 8
#define TT (BB*NN)

// ---------------- scratch (no allocations allowed) ----------------
__device__ __half g_h1h[(size_t)TT * CC];            // LN1 output (fp16)
__device__ __nv_bfloat16 g_qb[(size_t)TT * CC];      // Q  [b][h][n][d]  (pre-scaled)
__device__ __nv_bfloat16 g_kb[(size_t)TT * CC];      // K  [b][h][n][d]
__device__ __nv_bfloat16 g_vb[(size_t)TT * CC];      // V  [b][h][n][d]
__device__ __half g_oh[(size_t)TT * CC];             // attention output (fp16)
__device__ __half g_h2h[(size_t)TT * CC];            // LN2 output (fp16, MoE A)
__device__ __half g_qkvwT[(size_t)3 * CC * CC];      // fp16 transposed weights [n][k]
__device__ __half g_projwT[(size_t)CC * CC];
__device__ __half g_expwT[(size_t)EE * CC * CC];
__device__ int   g_cnt[EE];
__device__ int   g_list[EE * TT];
__device__ float g_wt[EE * TT];

// ---------------- helpers ----------------
__device__ __forceinline__ unsigned f2bf2(float lo, float hi) {
    __nv_bfloat162 h = __floats2bfloat162_rn(lo, hi);
    return *reinterpret_cast<unsigned*>(&h);
}
__device__ __forceinline__ void mma16(float* c, const unsigned* a, unsigned b0, unsigned b1) {
    asm volatile("mma.sync.aligned.m16n8k16.row.col.f32.bf16.bf16.f32 "
        "{%0,%1,%2,%3}, {%4,%5,%6,%7}, {%8,%9}, {%0,%1,%2,%3};"
        : "+f"(c[0]), "+f"(c[1]), "+f"(c[2]), "+f"(c[3])
        : "r"(a[0]), "r"(a[1]), "r"(a[2]), "r"(a[3]), "r"(b0), "r"(b1));
}
__device__ __forceinline__ void mma16h(float* c, const unsigned* a, unsigned b0, unsigned b1) {
    asm volatile("mma.sync.aligned.m16n8k16.row.col.f32.f16.f16.f32 "
        "{%0,%1,%2,%3}, {%4,%5,%6,%7}, {%8,%9}, {%0,%1,%2,%3};"
        : "+f"(c[0]), "+f"(c[1]), "+f"(c[2]), "+f"(c[3])
        : "r"(a[0]), "r"(a[1]), "r"(a[2]), "r"(a[3]), "r"(b0), "r"(b1));
}
__device__ __forceinline__ void cp16(unsigned dst, const void* src, int sz) {
    asm volatile("cp.async.cg.shared.global [%0], [%1], 16, %2;"
        :: "r"(dst), "l"(src), "r"(sz) : "memory");
}
__device__ __forceinline__ void ldsm4(unsigned& r0, unsigned& r1, unsigned& r2, unsigned& r3,
                                      unsigned addr) {
    asm volatile("ldmatrix.sync.aligned.m8n8.x4.shared.b16 {%0,%1,%2,%3}, [%4];"
        : "=r"(r0), "=r"(r1), "=r"(r2), "=r"(r3) : "r"(addr));
}

// ---------------- weight transposes -> fp16 [n][k] ----------------
__global__ __launch_bounds__(256) void transpose_half_kernel(
    const float* __restrict__ in, __half* __restrict__ out, int R, int Cc)
{
    __shared__ float t[32][33];
    int bx = blockIdx.x * 32, by = blockIdx.y * 32;
    int tx = threadIdx.x & 31, ty = threadIdx.x >> 5;
    #pragma unroll
    for (int j = 0; j < 4; j++)
        t[ty + j * 8][tx] = in[(size_t)(by + ty + j * 8) * Cc + bx + tx];
    __syncthreads();
    #pragma unroll
    for (int j = 0; j < 4; j++)
        out[(size_t)(bx + ty + j * 8) * R + by + tx] = __float2half_rn(t[tx][ty + j * 8]);
}

__global__ __launch_bounds__(256) void transpose_ep_kernel(
    const float* __restrict__ exp_w, __half* __restrict__ expT,
    const float* __restrict__ proj_w, __half* __restrict__ projT)
{
    __shared__ float t[32][33];
    int z = blockIdx.z;
    const float* in = (z < EE) ? exp_w + (size_t)z * CC * CC : proj_w;
    __half* out = (z < EE) ? expT + (size_t)z * CC * CC : projT;
    int bx = blockIdx.x * 32, by = blockIdx.y * 32;
    int tx = threadIdx.x & 31, ty = threadIdx.x >> 5;
    #pragma unroll
    for (int j = 0; j < 4; j++)
        t[ty + j * 8][tx] = in[(size_t)(by + ty + j * 8) * CC + bx + tx];
    __syncthreads();
    #pragma unroll
    for (int j = 0; j < 4; j++)
        out[(size_t)(bx + ty + j * 8) * CC + by + tx] = __float2half_rn(t[tx][ty + j * 8]);
}

// ---------------- LN1 (zeroes g_cnt in block 0) ----------------
__global__ __launch_bounds__(192) void ln1_kernel(const float* __restrict__ in,
    const float* __restrict__ gamma, const float* __restrict__ beta,
    __half* __restrict__ outh)
{
    if (blockIdx.x == 0 && threadIdx.x < EE) g_cnt[threadIdx.x] = 0;
    int t = blockIdx.x;
    int c = threadIdx.x * 4;
    const float* row = in + (size_t)t * CC;
    float4 v4 = *(const float4*)(row + c);
    float s = v4.x + v4.y + v4.z + v4.w;
    float s2 = v4.x * v4.x + v4.y * v4.y + v4.z * v4.z + v4.w * v4.w;
    __shared__ float sh[16];
    #pragma unroll
    for (int o = 16; o > 0; o >>= 1) { s += __shfl_xor_sync(~0u, s, o); s2 += __shfl_xor_sync(~0u, s2, o); }
    int w = threadIdx.x >> 5, l = threadIdx.x & 31;
    if (l == 0) { sh[w] = s; sh[8 + w] = s2; }
    __syncthreads();
    if (threadIdx.x == 0) {
        float a = 0.f, b = 0.f;
        #pragma unroll
        for (int i = 0; i < 6; i++) { a += sh[i]; b += sh[8 + i]; }
        sh[0] = a; sh[1] = b;
    }
    __syncthreads();
    float mean = sh[0] * (1.f / CC);
    float rstd = rsqrtf(sh[1] * (1.f / CC) - mean * mean + 1e-5f);
    float4 gv = *(const float4*)(gamma + c);
    float4 bv = *(const float4*)(beta + c);
    __half2* op = (__half2*)(outh + (size_t)t * CC + c);
    op[0] = __floats2half2_rn((v4.x - mean) * rstd * gv.x + bv.x, (v4.y - mean) * rstd * gv.y + bv.y);
    op[1] = __floats2half2_rn((v4.z - mean) * rstd * gv.z + bv.z, (v4.w - mean) * rstd * gv.w + bv.w);
}

// ---------------- fused LN2 + router ----------------
__global__ __launch_bounds__(192) void ln2_route_kernel(const float* __restrict__ in,
    const float* __restrict__ gamma, const float* __restrict__ beta,
    __half* __restrict__ outh,
    const float* __restrict__ route_w, const float* __restrict__ route_b,
    const float* __restrict__ rln_g, const float* __restrict__ rln_b,
    const float* __restrict__ noise)
{
    int t = blockIdx.x;
    int c = threadIdx.x * 4;
    const float* row = in + (size_t)t * CC;
    float4 v4 = *(const float4*)(row + c);
    float s = v4.x + v4.y + v4.z + v4.w;
    float s2 = v4.x * v4.x + v4.y * v4.y + v4.z * v4.z + v4.w * v4.w;
    __shared__ float sh[16];
    __shared__ float shacc[6][EE];
    #pragma unroll
    for (int o = 16; o > 0; o >>= 1) { s += __shfl_xor_sync(~0u, s, o); s2 += __shfl_xor_sync(~0u, s2, o); }
    int w = threadIdx.x >> 5, l = threadIdx.x & 31;
    if (l == 0) { sh[w] = s; sh[8 + w] = s2; }
    __syncthreads();
    if (threadIdx.x == 0) {
        float a = 0.f, b = 0.f;
        #pragma unroll
        for (int i = 0; i < 6; i++) { a += sh[i]; b += sh[8 + i]; }
        sh[0] = a; sh[1] = b;
    }
    __syncthreads();
    float mean = sh[0] * (1.f / CC);
    float rstd = rsqrtf(sh[1] * (1.f / CC) - mean * mean + 1e-5f);
    float4 gv = *(const float4*)(gamma + c);
    float4 bv = *(const float4*)(beta + c);
    float v[4];
    v[0] = (v4.x - mean) * rstd * gv.x + bv.x;
    v[1] = (v4.y - mean) * rstd * gv.y + bv.y;
    v[2] = (v4.z - mean) * rstd * gv.z + bv.z;
    v[3] = (v4.w - mean) * rstd * gv.w + bv.w;
    __half2* op = (__half2*)(outh + (size_t)t * CC + c);
    op[0] = __floats2half2_rn(v[0], v[1]);
    op[1] = __floats2half2_rn(v[2], v[3]);

    float acc[EE];
    #pragma unroll
    for (int e = 0; e < EE; e++) acc[e] = 0.f;
    #pragma unroll
    for (int i = 0; i < 4; i++) {
        const float4* rw = (const float4*)(route_w + (size_t)(c + i) * EE);
        float4 r0 = rw[0], r1 = rw[1];
        acc[0] += v[i] * r0.x; acc[1] += v[i] * r0.y;
        acc[2] += v[i] * r0.z; acc[3] += v[i] * r0.w;
        acc[4] += v[i] * r1.x; acc[5] += v[i] * r1.y;
        acc[6] += v[i] * r1.z; acc[7] += v[i] * r1.w;
    }
    #pragma unroll
    for (int e = 0; e < EE; e++)
        #pragma unroll
        for (int o = 16; o > 0; o >>= 1)
            acc[e] += __shfl_xor_sync(~0u, acc[e], o);
    if (l == 0) {
        #pragma unroll
        for (int e = 0; e < EE; e++) shacc[w][e] = acc[e];
    }
    __syncthreads();
    if (threadIdx.x == 0) {
        float lg[EE];
        float lmean = 0.f;
        #pragma unroll
        for (int e = 0; e < EE; e++) {
            float a = 0.f;
            #pragma unroll
            for (int i = 0; i < 6; i++) a += shacc[i][e];
            lg[e] = a + route_b[e];
            lmean += lg[e];
        }
        lmean *= (1.f / EE);
        float var = 0.f;
        #pragma unroll
        for (int e = 0; e < EE; e++) { float d = lg[e] - lmean; var += d * d; }
        var *= (1.f / EE);
        float lrstd = rsqrtf(var + 1e-5f);
        float mx = -1e30f;
        #pragma unroll
        for (int e = 0; e < EE; e++) { lg[e] = (lg[e] - lmean) * lrstd * rln_g[e] + rln_b[e]; mx = fmaxf(mx, lg[e]); }
        float den = 0.f;
        float r[EE];
        #pragma unroll
        for (int e = 0; e < EE; e++) { r[e] = __expf(lg[e] - mx); den += r[e]; }
        float inv = 1.f / den;
        const float* nrow = noise + (size_t)t * EE;
        #pragma unroll
        for (int e = 0; e < EE; e++) r[e] = r[e] * inv + nrow[e] * 0.125f;

        int i1 = 0;
        #pragma unroll
        for (int e = 1; e < EE; e++) if (r[e] > r[i1]) i1 = e;
        int i2 = (i1 == 0) ? 1 : 0;
        #pragma unroll
        for (int e = 0; e < EE; e++) if (e != i1 && r[e] > r[i2]) i2 = e;

        float vm = fmaxf(r[i1], r[i2]);
        float e1 = __expf(r[i1] - vm), e2 = __expf(r[i2] - vm);
        float wsum = 1.f / (e1 + e2);
        float w1 = e1 * wsum, w2 = e2 * wsum;

        int p1 = atomicAdd(&g_cnt[i1], 1);
        g_list[i1 * TT + p1] = t; g_wt[i1 * TT + p1] = w1;
        int p2 = atomicAdd(&g_cnt[i2], 1);
        g_list[i2 * TT + p2] = t; g_wt[i2 * TT + p2] = w2;
    }
}

// ---------------- fp16 GEMM, 128x128x32, 4-stage cp.async, ldmatrix frags ----------------
#define BM 128
#define BN 128
#define GS 4
#define QAW 20
#define QSTG_W (BM * QAW)
#define GEMM_SMEM ((2 * GS * QSTG_W + 384) * 4)

template<int MODE>
__global__ __launch_bounds__(256, 2) void fp16_gemm_kernel(
    const __half* __restrict__ A, const __half* __restrict__ BT, float* __restrict__ Cm,
    int Nn,
    const float* __restrict__ bias, const float* __restrict__ resid,
    __nv_bfloat16* __restrict__ qb, __nv_bfloat16* __restrict__ kb,
    __nv_bfloat16* __restrict__ vb)
{
    extern __shared__ unsigned qsm[];
    unsigned* As = qsm;
    unsigned* Bs = As + GS * QSTG_W;
    int*   stok = (int*)(Bs + GS * QSTG_W);
    float* swt  = (float*)(stok + BM);
    const int K = CC;

    int bm = blockIdx.y * BM, bn = blockIdx.x * BN;
    int tid = threadIdx.x;
    int e = 0;
    if (MODE == 1) {
        e = blockIdx.z;
        int cnt = g_cnt[e];
        if (bm >= cnt) return;
        if (tid < BM) {
            int m = bm + tid;
            if (m < cnt) { stok[tid] = g_list[e * TT + m]; swt[tid] = g_wt[e * TT + m]; }
            else         { stok[tid] = -1; swt[tid] = 0.f; }
        }
        __syncthreads();
    }

    const __half* BTb = (MODE == 1) ? (BT + (size_t)e * K * Nn) : BT;
    unsigned a_smem = (unsigned)__cvta_generic_to_shared(As);
    unsigned b_smem = (unsigned)__cvta_generic_to_shared(Bs);

    int rowF = tid >> 1;
    int segF = (tid & 1) * 2;

    auto fill_stage = [&](int s, int k0) {
        #pragma unroll
        for (int j = 0; j < 2; j++) {
            int seg = segF + j;
            const __half* srcA;
            int sz = 16;
            if (MODE == 1) {
                int tok = stok[rowF];
                if (tok >= 0) srcA = A + (size_t)tok * K + k0 + seg * 8;
                else { srcA = A; sz = 0; }
            } else {
                srcA = A + (size_t)(bm + rowF) * K + k0 + seg * 8;
            }
            cp16(a_smem + (unsigned)((s * QSTG_W + rowF * QAW + seg * 4) * 4), srcA, sz);
            const __half* srcB = BTb + (size_t)(bn + rowF) * K + k0 + seg * 8;
            cp16(b_smem + (unsigned)((s * QSTG_W + rowF * QAW + seg * 4) * 4), srcB, 16);
        }
    };

    #pragma unroll
    for (int s = 0; s < GS - 1; s++) {
        fill_stage(s, s * 32);
        asm volatile("cp.async.commit_group;" ::: "memory");
    }

    int lane = tid & 31, wid = tid >> 5;
    int wm = (wid & 3) * 32;
    int wn = (wid >> 2) * 64;
    int g = lane >> 2, c = lane & 3;

    // ---- per-lane ldmatrix word offsets (kc=0), within a stage ----
    // A frag (per mi): tiles (r,k0),(r+8,k0),(r,k8),(r+8,k8); lane l -> tile l>>3, row l&7
    int lrow8 = lane & 7;
    int ltile01 = (lane >> 3) & 1;   // row +8 selector for A ; k +8 selector for B
    int ltile2  = (lane >> 4) & 1;   // k +8 selector for A  ; n +8 selector for B
    unsigned aoff[2], boff[4];
    #pragma unroll
    for (int mi = 0; mi < 2; mi++)
        aoff[mi] = (unsigned)((wm + mi * 16 + lrow8 + ltile01 * 8) * QAW + ltile2 * 4);
    #pragma unroll
    for (int p = 0; p < 4; p++)
        boff[p] = (unsigned)((wn + p * 16 + lrow8 + ltile2 * 8) * QAW + ltile01 * 4);

    float acc[2][8][4];
    #pragma unroll
    for (int mi = 0; mi < 2; mi++)
        #pragma unroll
        for (int ni = 0; ni < 8; ni++)
            #pragma unroll
            for (int q = 0; q < 4; q++) acc[mi][ni][q] = 0.f;

    int nIter = K / 32;
    for (int it = 0; it < nIter; it++) {
        asm volatile("cp.async.wait_group 2;" ::: "memory");
        __syncthreads();

        int nx = it + GS - 1;
        if (nx < nIter) fill_stage(nx & (GS - 1), nx * 32);
        asm volatile("cp.async.commit_group;" ::: "memory");

        unsigned stb = (unsigned)((it & (GS - 1)) * QSTG_W * 4);
        unsigned ab = a_smem + stb, bb = b_smem + stb;
        #pragma unroll
        for (int kc = 0; kc < 2; kc++) {
            unsigned kadd = (unsigned)(kc * 8 * 4);
            unsigned af[2][4], bf[4][4];
            ldsm4(af[0][0], af[0][1], af[0][2], af[0][3], ab + aoff[0] * 4 + kadd);
            ldsm4(af[1][0], af[1][1], af[1][2], af[1][3], ab + aoff[1] * 4 + kadd);
            #pragma unroll
            for (int p = 0; p < 4; p++)
                ldsm4(bf[p][0], bf[p][1], bf[p][2], bf[p][3], bb + boff[p] * 4 + kadd);
            #pragma unroll
            for (int ni = 0; ni < 8; ni++) {
                unsigned b0 = bf[ni >> 1][(ni & 1) * 2];
                unsigned b1 = bf[ni >> 1][(ni & 1) * 2 + 1];
                mma16h(acc[0][ni], af[0], b0, b1);
                mma16h(acc[1][ni], af[1], b0, b1);
            }
        }
    }

    #pragma unroll
    for (int mi = 0; mi < 2; mi++) {
        int rl0 = wm + mi * 16 + g;
        int rl1 = rl0 + 8;
        if (MODE == 1) {
            int tk0 = stok[rl0], tk1 = stok[rl1];
            float w0 = swt[rl0], w1 = swt[rl1];
            #pragma unroll
            for (int ni = 0; ni < 8; ni++) {
                int cn = bn + wn + ni * 8 + 2 * c;
                float b0 = bias[(size_t)e * Nn + cn], b1 = bias[(size_t)e * Nn + cn + 1];
                if (tk0 >= 0) {
                    float* p = Cm + (size_t)tk0 * Nn + cn;
                    atomicAdd(p,     w0 * (acc[mi][ni][0] + b0));
                    atomicAdd(p + 1, w0 * (acc[mi][ni][1] + b1));
                }
                if (tk1 >= 0) {
                    float* p = Cm + (size_t)tk1 * Nn + cn;
                    atomicAdd(p,     w1 * (acc[mi][ni][2] + b0));
                    atomicAdd(p + 1, w1 * (acc[mi][ni][3] + b1));
                }
            }
        } else if (MODE == 2) {
            int r0 = bm + rl0, r1 = bm + rl1;
            int b0r = r0 >> 10, n0 = r0 & 1023;
            int b1r = r1 >> 10, n1 = r1 & 1023;
            #pragma unroll
            for (int ni = 0; ni < 8; ni++) {
                int cn = bn + wn + ni * 8 + 2 * c;
                int sect = cn / CC;
                int cc = cn - sect * CC;
                int h = cc >> 6, d = cc & 63;
                size_t i0 = ((size_t)(b0r * HH + h) * NN + n0) * DH + d;
                size_t i1 = ((size_t)(b1r * HH + h) * NN + n1) * DH + d;
                if (sect == 0) {
                    *(unsigned*)&qb[i0] = f2bf2(acc[mi][ni][0] * 0.125f, acc[mi][ni][1] * 0.125f);
                    *(unsigned*)&qb[i1] = f2bf2(acc[mi][ni][2] * 0.125f, acc[mi][ni][3] * 0.125f);
                } else if (sect == 1) {
                    *(unsigned*)&kb[i0] = f2bf2(acc[mi][ni][0], acc[mi][ni][1]);
                    *(unsigned*)&kb[i1] = f2bf2(acc[mi][ni][2], acc[mi][ni][3]);
                } else {
                    *(unsigned*)&vb[i0] = f2bf2(acc[mi][ni][0], acc[mi][ni][1]);
                    *(unsigned*)&vb[i1] = f2bf2(acc[mi][ni][2], acc[mi][ni][3]);
                }
            }
        } else {
            int r0 = bm + rl0, r1 = bm + rl1;
            #pragma unroll
            for (int ni = 0; ni < 8; ni++) {
                int cn = bn + wn + ni * 8 + 2 * c;
                float2 v0 = make_float2(acc[mi][ni][0], acc[mi][ni][1]);
                float2 v1 = make_float2(acc[mi][ni][2], acc[mi][ni][3]);
                float b0 = bias[cn], b1 = bias[cn + 1];
                v0.x += b0; v0.y += b1; v1.x += b0; v1.y += b1;
                float2 r0v = *(const float2*)(resid + (size_t)r0 * Nn + cn);
                float2 r1v = *(const float2*)(resid + (size_t)r1 * Nn + cn);
                v0.x += r0v.x; v0.y += r0v.y; v1.x += r1v.x; v1.y += r1v.y;
                *(float2*)(Cm + (size_t)r0 * Nn + cn) = v0;
                *(float2*)(Cm + (size_t)r1 * Nn + cn) = v1;
            }
        }
    }
}

// ---------------- bf16 flash attention (V transposed in smem fill) ----------------
#define QSTRW 36
#define KSTRW 36
#define ATTN_SMEM ((128*QSTRW + 2*64*KSTRW + 2*64*KSTRW) * 4)

__global__ __launch_bounds__(256, 2) void attn_bf16_kernel(
    const __nv_bfloat16* __restrict__ qb,
    const __nv_bfloat16* __restrict__ kb,
    const __nv_bfloat16* __restrict__ vb,
    __half* __restrict__ o)
{
    extern __shared__ unsigned smem_u[];
    unsigned* QPs = smem_u;
    unsigned* Ks  = QPs + 128 * QSTRW;
    unsigned* Vs  = Ks + 2 * 64 * KSTRW;

    int bh = blockIdx.y;
    int bb = bh / HH, hh = bh % HH;
    int q0 = blockIdx.x * 128;
    int tid = threadIdx.x;
    int lane = tid & 31, wid = tid >> 5;
    int wm = wid * 16;
    int g = lane >> 2, c = lane & 3;

    const __nv_bfloat16* q_head = qb + ((size_t)(bb * HH + hh) * NN + q0) * DH;
    const __nv_bfloat16* k_head = kb + (size_t)(bb * HH + hh) * NN * DH;
    const __nv_bfloat16* v_head = vb + (size_t)(bb * HH + hh) * NN * DH;

    {
        int row = tid >> 1, seg = tid & 1;
        const uint4* src = (const uint4*)(q_head + (size_t)row * DH + seg * 32);
        unsigned* dst = QPs + row * QSTRW + seg * 16;
        #pragma unroll
        for (int i = 0; i < 4; i++)
            *(uint4*)(dst + i * 4) = src[i];
    }
    __syncthreads();

    unsigned qf[4][4];
    #pragma unroll
    for (int kc = 0; kc < 4; kc++) {
        int bw = kc * 8 + c;
        qf[kc][0] = QPs[(wm + g) * QSTRW + bw];
        qf[kc][1] = QPs[(wm + g + 8) * QSTRW + bw];
        qf[kc][2] = QPs[(wm + g) * QSTRW + bw + 4];
        qf[kc][3] = QPs[(wm + g + 8) * QSTRW + bw + 4];
    }
    __syncthreads();

    float oacc[8][4];
    #pragma unroll
    for (int ni = 0; ni < 8; ni++)
        #pragma unroll
        for (int q = 0; q < 4; q++) oacc[ni][q] = 0.f;
    float m0 = -1e30f, m1 = -1e30f, l0 = 0.f, l1 = 0.f;

    int ktok = tid & 63, kseg = tid >> 6;

    __nv_bfloat16* Vh0 = (__nv_bfloat16*)Vs;
    auto store_v = [&](__nv_bfloat16* Vh, int seg, uint4 u) {
        const __nv_bfloat16* p = (const __nv_bfloat16*)&u;
        #pragma unroll
        for (int i = 0; i < 8; i++)
            Vh[(seg * 8 + i) * 72 + ktok] = p[i];
    };

    {
        const uint4* ksrc = (const uint4*)(k_head + (size_t)ktok * DH);
        *(uint4*)(Ks + ktok * KSTRW + kseg * 4) = ksrc[kseg];
        *(uint4*)(Ks + ktok * KSTRW + (kseg + 4) * 4) = ksrc[kseg + 4];
        const uint4* vsrc = (const uint4*)(v_head + (size_t)ktok * DH);
        store_v(Vh0, kseg, vsrc[kseg]);
        store_v(Vh0, kseg + 4, vsrc[kseg + 4]);
    }
    __syncthreads();

    const int NTILES = NN / 64;
    for (int tile = 0; tile < NTILES; tile++) {
        int cur = tile & 1, nxt = cur ^ 1;
        const unsigned* Kb = Ks + cur * 64 * KSTRW;
        const unsigned* Vb = Vs + cur * 64 * KSTRW;
        bool more = (tile + 1 < NTILES);

        uint4 kx0, kx1, vx0, vx1;
        if (more) {
            const uint4* ksrc = (const uint4*)(k_head + (size_t)(tile + 1) * 64 * DH + (size_t)ktok * DH);
            kx0 = ksrc[kseg]; kx1 = ksrc[kseg + 4];
            const uint4* vsrc = (const uint4*)(v_head + (size_t)(tile + 1) * 64 * DH + (size_t)ktok * DH);
            vx0 = vsrc[kseg]; vx1 = vsrc[kseg + 4];
        }

        float sa[8][4];
        #pragma unroll
        for (int ni = 0; ni < 8; ni++)
            #pragma unroll
            for (int q = 0; q < 4; q++) sa[ni][q] = 0.f;
        #pragma unroll
        for (int kc = 0; kc < 4; kc++) {
            #pragma unroll
            for (int ni = 0; ni < 8; ni++) {
                int bw = (ni * 8 + g) * KSTRW + kc * 8 + c;
                mma16(sa[ni], qf[kc], Kb[bw], Kb[bw + 4]);
            }
        }

        float mx0 = -1e30f, mx1 = -1e30f;
        #pragma unroll
        for (int ni = 0; ni < 8; ni++) {
            mx0 = fmaxf(mx0, fmaxf(sa[ni][0], sa[ni][1]));
            mx1 = fmaxf(mx1, fmaxf(sa[ni][2], sa[ni][3]));
        }
        mx0 = fmaxf(mx0, __shfl_xor_sync(~0u, mx0, 1));
        mx0 = fmaxf(mx0, __shfl_xor_sync(~0u, mx0, 2));
        mx1 = fmaxf(mx1, __shfl_xor_sync(~0u, mx1, 1));
        mx1 = fmaxf(mx1, __shfl_xor_sync(~0u, mx1, 2));
        float mn0 = fmaxf(m0, mx0), mn1 = fmaxf(m1, mx1);
        float al0 = __expf(m0 - mn0), al1 = __expf(m1 - mn1);
        float sum0 = 0.f, sum1 = 0.f;
        #pragma unroll
        for (int ni = 0; ni < 8; ni++) {
            float p00 = __expf(sa[ni][0] - mn0);
            float p01 = __expf(sa[ni][1] - mn0);
            float p10 = __expf(sa[ni][2] - mn1);
            float p11 = __expf(sa[ni][3] - mn1);
            sum0 += p00 + p01; sum1 += p10 + p11;
            QPs[(wm + g) * QSTRW + ni * 4 + c]     = f2bf2(p00, p01);
            QPs[(wm + g + 8) * QSTRW + ni * 4 + c] = f2bf2(p10, p11);
        }
        sum0 += __shfl_xor_sync(~0u, sum0, 1);
        sum0 += __shfl_xor_sync(~0u, sum0, 2);
        sum1 += __shfl_xor_sync(~0u, sum1, 1);
        sum1 += __shfl_xor_sync(~0u, sum1, 2);
        l0 = l0 * al0 + sum0; l1 = l1 * al1 + sum1;
        m0 = mn0; m1 = mn1;
        #pragma unroll
        for (int ni = 0; ni < 8; ni++) {
            oacc[ni][0] *= al0; oacc[ni][1] *= al0;
            oacc[ni][2] *= al1; oacc[ni][3] *= al1;
        }
        __syncwarp();

        if (more) {
            unsigned* Kn = Ks + nxt * 64 * KSTRW;
            *(uint4*)(Kn + ktok * KSTRW + kseg * 4) = kx0;
            *(uint4*)(Kn + ktok * KSTRW + (kseg + 4) * 4) = kx1;
        }

        #pragma unroll
        for (int kc = 0; kc < 4; kc++) {
            unsigned af[4];
            int bw = kc * 8 + c;
            af[0] = QPs[(wm + g) * QSTRW + bw];
            af[1] = QPs[(wm + g + 8) * QSTRW + bw];
            af[2] = QPs[(wm + g) * QSTRW + bw + 4];
            af[3] = QPs[(wm + g + 8) * QSTRW + bw + 4];
            #pragma unroll
            for (int ni = 0; ni < 8; ni++) {
                int vw = (ni * 8 + g) * KSTRW + kc * 8 + c;
                mma16(oacc[ni], af, Vb[vw], Vb[vw + 4]);
            }
        }

        if (more) {
            __nv_bfloat16* Vn = (__nv_bfloat16*)(Vs + nxt * 64 * KSTRW);
            store_v(Vn, kseg, vx0);
            store_v(Vn, kseg + 4, vx1);
        }
        __syncthreads();
    }

    float inv0 = 1.f / l0, inv1 = 1.f / l1;
    size_t t0 = (size_t)bb * NN + q0 + wm + g;
    size_t t1 = t0 + 8;
    #pragma unroll
    for (int ni = 0; ni < 8; ni++) {
        int dcol = hh * DH + ni * 8 + 2 * c;
        *(__half2*)&o[t0 * CC + dcol] = __floats2half2_rn(oacc[ni][0] * inv0, oacc[ni][1] * inv0);
        *(__half2*)&o[t1 * CC + dcol] = __floats2half2_rn(oacc[ni][2] * inv1, oacc[ni][3] * inv1);
    }
}

// ---------------- launch ----------------
extern "C" void kernel_launch(void* const* d_in, const int* in_sizes, int n_in,
                              void* d_out, int out_size)
{
    const float* x       = (const float*)d_in[0];
    const float* noise   = (const float*)d_in[1];
    const float* ln1_g   = (const float*)d_in[2];
    const float* ln1_b   = (const float*)d_in[3];
    const float* qkv_w   = (const float*)d_in[4];
    const float* proj_w  = (const float*)d_in[5];
    const float* proj_b  = (const float*)d_in[6];
    const float* ln2_g   = (const float*)d_in[7];
    const float* ln2_b   = (const float*)d_in[8];
    const float* route_w = (const float*)d_in[9];
    const float* route_b = (const float*)d_in[10];
    const float* rln_g   = (const float*)d_in[11];
    const float* rln_b   = (const float*)d_in[12];
    const float* exp_w   = (const float*)d_in[13];
    const float* exp_b   = (const float*)d_in[14];
    float* out = (float*)d_out;

    __half *h1h, *oh, *h2h, *qkvwT, *projwT, *expwT;
    __nv_bfloat16 *qbp, *kbp, *vbp;
    cudaGetSymbolAddress((void**)&h1h, g_h1h);
    cudaGetSymbolAddress((void**)&oh,  g_oh);
    cudaGetSymbolAddress((void**)&h2h, g_h2h);
    cudaGetSymbolAddress((void**)&qkvwT,  g_qkvwT);
    cudaGetSymbolAddress((void**)&projwT, g_projwT);
    cudaGetSymbolAddress((void**)&expwT,  g_expwT);
    cudaGetSymbolAddress((void**)&qbp, g_qb);
    cudaGetSymbolAddress((void**)&kbp, g_kb);
    cudaGetSymbolAddress((void**)&vbp, g_vb);

    cudaFuncSetAttribute(attn_bf16_kernel, cudaFuncAttributeMaxDynamicSharedMemorySize, (int)ATTN_SMEM);
    cudaFuncSetAttribute(fp16_gemm_kernel<0>, cudaFuncAttributeMaxDynamicSharedMemorySize, (int)GEMM_SMEM);
    cudaFuncSetAttribute(fp16_gemm_kernel<1>, cudaFuncAttributeMaxDynamicSharedMemorySize, (int)GEMM_SMEM);
    cudaFuncSetAttribute(fp16_gemm_kernel<2>, cudaFuncAttributeMaxDynamicSharedMemorySize, (int)GEMM_SMEM);

    // 0) weight transposes -> fp16 [n][k]
    transpose_half_kernel<<<dim3(3 * CC / 32, CC / 32), 256>>>(qkv_w, qkvwT, CC, 3 * CC);
    transpose_ep_kernel<<<dim3(CC / 32, CC / 32, EE + 1), 256>>>(exp_w, expwT, proj_w, projwT);
    // 1) LN1 -> fp16 h1 (+ zero g_cnt)
    ln1_kernel<<<TT, 192>>>(x, ln1_g, ln1_b, h1h);
    // 2) QKV GEMM (fp16 mma + ldmatrix) -> bf16 q/k/v
    fp16_gemm_kernel<2><<<dim3(3 * CC / BN, TT / BM), 256, GEMM_SMEM>>>(
        h1h, qkvwT, nullptr, 3 * CC, nullptr, nullptr, qbp, kbp, vbp);
    // 3) attention -> fp16 o
    attn_bf16_kernel<<<dim3(NN / 128, BB * HH), 256, ATTN_SMEM>>>(qbp, kbp, vbp, oh);
    // 4) proj + bias + residual -> d_out
    fp16_gemm_kernel<0><<<dim3(CC / BN, TT / BM), 256, GEMM_SMEM>>>(
        oh, projwT, out, CC, proj_b, x, nullptr, nullptr, nullptr);
    // 5) fused LN2 + router -> fp16 h2h + expert lists
    ln2_route_kernel<<<TT, 192>>>(out, ln2_g, ln2_b, h2h,
                                  route_w, route_b, rln_g, rln_b, noise);
    // 6) MoE grouped GEMM (fp16 mma), atomicAdd into d_out
    fp16_gemm_kernel<1><<<dim3(CC / BN, TT / BM, EE), 256, GEMM_SMEM>>>(
        h2h, expwT, out, CC, exp_b, nullptr, nullptr, nullptr, nullptr);
}